// round 9
// baseline (speedup 1.0000x reference)
#include <cuda_runtime.h>
#include <cstdint>

#define NB    8
#define SEQ   1024
#define CH    576
#define NHEAD 6
#define HDIM  96

// raw projection outputs (scrambled view [b][h][d][t])
__device__ float g_Q[NB*SEQ*CH];
__device__ float g_K[NB*SEQ*CH];
__device__ float g_V[NB*SEQ*CH];

// pre-decomposed, tile-layout K and V for the attention kernel.
// K tile: [96 rows][104], slot(d, k) = d*104 + (k&7)*12 + (k>>3)   (k = t&63)
// V tile: [64 rows][104], slot(k, d) = k*104 + (d&7)*12 + (d>>3)
#define KT_FLOATS 9984      // 96*104
#define VT_FLOATS 6656      // 64*104
#define NTILE     16
__device__ float g_KhiP[NB*NHEAD*NTILE*KT_FLOATS];
__device__ float g_KloP[NB*NHEAD*NTILE*KT_FLOATS];
__device__ float g_VP  [NB*NHEAD*NTILE*VT_FLOATS];

__device__ __forceinline__ uint32_t f2tf(float x) {
    uint32_t u;
    asm("cvt.rna.tf32.f32 %0, %1;" : "=r"(u) : "f"(x));
    return u;
}

__device__ __forceinline__ void mma_tf32(float& d0, float& d1, float& d2, float& d3,
                                         uint32_t a0, uint32_t a1, uint32_t a2, uint32_t a3,
                                         uint32_t b0, uint32_t b1) {
    asm volatile(
        "mma.sync.aligned.m16n8k8.row.col.f32.tf32.tf32.f32 "
        "{%0,%1,%2,%3},{%4,%5,%6,%7},{%8,%9},{%0,%1,%2,%3};"
        : "+f"(d0), "+f"(d1), "+f"(d2), "+f"(d3)
        : "r"(a0), "r"(a1), "r"(a2), "r"(a3), "r"(b0), "r"(b1));
}

__device__ __forceinline__ void cp16(uint32_t dst_smem, const void* src) {
    asm volatile("cp.async.cg.shared.global [%0], [%1], 16;\n"
                 :: "r"(dst_smem), "l"(src));
}
#define CP_COMMIT() asm volatile("cp.async.commit_group;\n" ::: "memory")
#define CP_WAIT(n)  asm volatile("cp.async.wait_group %0;\n" :: "n"(n) : "memory")

// ---------------------------------------------------------------------------
// Projection: Y = X @ W^T + bias.  One launch, z={Q,K,V}; runtime SPLIT:
// 3x-tf32 for Q,K; single tf32 for V.
// ---------------------------------------------------------------------------
#define PROJ_SMEM_BYTES ((2*128*36 + 2*64*36) * 4)

__global__ __launch_bounds__(256) void proj_mma(
    const float* __restrict__ x1, const float* __restrict__ x2,
    const float* __restrict__ Wq, const float* __restrict__ bq,
    const float* __restrict__ Wk, const float* __restrict__ bk,
    const float* __restrict__ Wv, const float* __restrict__ bv)
{
    const int which = blockIdx.z;
    const bool SPLIT = (which < 2);
    const float* X    = (which == 0) ? x1 : x2;
    const float* W    = (which == 0) ? Wq : (which == 1) ? Wk : Wv;
    const float* bias = (which == 0) ? bq : (which == 1) ? bk : bv;
    float*       Y    = (which == 0) ? g_Q : (which == 1) ? g_K : g_V;

    extern __shared__ float sp[];
    float* Xhi = sp;
    float* Whi = sp + 128*36;
    float* Xlo = sp + 128*36 + 64*36;
    float* Wlo = sp + 2*128*36 + 64*36;

    const int tid  = threadIdx.x;
    const int lane = tid & 31;
    const int w    = tid >> 5;
    const int wm   = w & 3, wn = w >> 2;
    const int r    = lane >> 2, c = lane & 3;
    const int n0   = blockIdx.x * 64;
    const int m0   = blockIdx.y * 128;

    float acc[2][4][4];
#pragma unroll
    for (int mi = 0; mi < 2; mi++)
#pragma unroll
        for (int f = 0; f < 4; f++)
#pragma unroll
            for (int j = 0; j < 4; j++) acc[mi][f][j] = 0.f;

    const int lrow = tid >> 3;
    const int lcol = (tid & 7) * 4;

    for (int c0 = 0; c0 < CH; c0 += 32) {
        __syncthreads();
#pragma unroll
        for (int p = 0; p < 4; p++) {
            int m = lrow + p * 32;
            float4 xv = *(const float4*)&X[(size_t)(m0 + m) * CH + c0 + lcol];
            float xs[4] = {xv.x, xv.y, xv.z, xv.w};
#pragma unroll
            for (int j = 0; j < 4; j++) {
                uint32_t hb = f2tf(xs[j]);
                Xhi[m * 36 + lcol + j] = __uint_as_float(hb);
                if (SPLIT)
                    Xlo[m * 36 + lcol + j] =
                        __uint_as_float(f2tf(xs[j] - __uint_as_float(hb)));
            }
        }
#pragma unroll
        for (int p = 0; p < 2; p++) {
            int n = lrow + p * 32;
            float4 wv = *(const float4*)&W[(size_t)(n0 + n) * CH + c0 + lcol];
            float ws[4] = {wv.x, wv.y, wv.z, wv.w};
#pragma unroll
            for (int j = 0; j < 4; j++) {
                uint32_t hb = f2tf(ws[j]);
                Whi[n * 36 + lcol + j] = __uint_as_float(hb);
                if (SPLIT)
                    Wlo[n * 36 + lcol + j] =
                        __uint_as_float(f2tf(ws[j] - __uint_as_float(hb)));
            }
        }
        __syncthreads();

#pragma unroll
        for (int ks = 0; ks < 4; ks++) {
            const int k = ks * 8 + c;
            uint32_t ahi[2][4], alo[2][4], bhi[4][2], blo[4][2];
#pragma unroll
            for (int mi = 0; mi < 2; mi++) {
                int mm = wm * 32 + mi * 16;
                ahi[mi][0] = __float_as_uint(Xhi[(mm + r) * 36 + k]);
                ahi[mi][1] = __float_as_uint(Xhi[(mm + r + 8) * 36 + k]);
                ahi[mi][2] = __float_as_uint(Xhi[(mm + r) * 36 + k + 4]);
                ahi[mi][3] = __float_as_uint(Xhi[(mm + r + 8) * 36 + k + 4]);
                if (SPLIT) {
                    alo[mi][0] = __float_as_uint(Xlo[(mm + r) * 36 + k]);
                    alo[mi][1] = __float_as_uint(Xlo[(mm + r + 8) * 36 + k]);
                    alo[mi][2] = __float_as_uint(Xlo[(mm + r) * 36 + k + 4]);
                    alo[mi][3] = __float_as_uint(Xlo[(mm + r + 8) * 36 + k + 4]);
                }
            }
#pragma unroll
            for (int f = 0; f < 4; f++) {
                int nn = wn * 32 + f * 8 + r;
                bhi[f][0] = __float_as_uint(Whi[nn * 36 + k]);
                bhi[f][1] = __float_as_uint(Whi[nn * 36 + k + 4]);
                if (SPLIT) {
                    blo[f][0] = __float_as_uint(Wlo[nn * 36 + k]);
                    blo[f][1] = __float_as_uint(Wlo[nn * 36 + k + 4]);
                }
            }
#pragma unroll
            for (int mi = 0; mi < 2; mi++)
#pragma unroll
                for (int f = 0; f < 4; f++) {
                    mma_tf32(acc[mi][f][0], acc[mi][f][1], acc[mi][f][2], acc[mi][f][3],
                             ahi[mi][0], ahi[mi][1], ahi[mi][2], ahi[mi][3],
                             bhi[f][0], bhi[f][1]);
                    if (SPLIT) {
                        mma_tf32(acc[mi][f][0], acc[mi][f][1], acc[mi][f][2], acc[mi][f][3],
                                 ahi[mi][0], ahi[mi][1], ahi[mi][2], ahi[mi][3],
                                 blo[f][0], blo[f][1]);
                        mma_tf32(acc[mi][f][0], acc[mi][f][1], acc[mi][f][2], acc[mi][f][3],
                                 alo[mi][0], alo[mi][1], alo[mi][2], alo[mi][3],
                                 bhi[f][0], bhi[f][1]);
                    }
                }
        }
    }

#pragma unroll
    for (int mi = 0; mi < 2; mi++)
#pragma unroll
        for (int f = 0; f < 4; f++) {
            int n = n0 + wn * 32 + f * 8 + 2 * c;
            float b0 = bias[n], b1 = bias[n + 1];
            int m = m0 + wm * 32 + mi * 16 + r;
            float2 o0 = make_float2(acc[mi][f][0] + b0, acc[mi][f][1] + b1);
            float2 o1 = make_float2(acc[mi][f][2] + b0, acc[mi][f][3] + b1);
            *(float2*)&Y[(size_t)m * CH + n] = o0;
            *(float2*)&Y[(size_t)(m + 8) * CH + n] = o1;
        }
}

// ---------------------------------------------------------------------------
// Repack: K -> (hi,lo) tf32 tiles, V -> tf32 tiles, in attn smem layout.
// 512 threads for latency hiding (was LDG-latency-bound at 256).
// ---------------------------------------------------------------------------
#define RK_SMEM_BYTES ((2*KT_FLOATS + VT_FLOATS) * 4)

__global__ __launch_bounds__(512) void repack_kv()
{
    extern __shared__ float s[];
    float* sKhi = s;
    float* sKlo = s + KT_FLOATS;
    float* sV   = s + 2*KT_FLOATS;

    const int tile = blockIdx.x, h = blockIdx.y, b = blockIdx.z;
    const size_t base = (size_t)b*(SEQ*CH) + (size_t)h*(HDIM*SEQ) + (size_t)tile*64;

    for (int idx = threadIdx.x; idx < HDIM*64; idx += 512) {
        int d = idx >> 6, k = idx & 63;
        float kv = g_K[base + (size_t)d*SEQ + k];
        uint32_t hi = f2tf(kv);
        int slot = d*104 + (k&7)*12 + (k>>3);
        sKhi[slot] = __uint_as_float(hi);
        sKlo[slot] = __uint_as_float(f2tf(kv - __uint_as_float(hi)));
        float vv = g_V[base + (size_t)d*SEQ + k];
        sV[k*104 + (d&7)*12 + (d>>3)] = __uint_as_float(f2tf(vv));
    }
    __syncthreads();

    size_t tb = (size_t)((b*NHEAD + h)*NTILE + tile);
    float* gkh = g_KhiP + tb * KT_FLOATS;
    float* gkl = g_KloP + tb * KT_FLOATS;
    float* gv  = g_VP   + tb * VT_FLOATS;
    for (int i = threadIdx.x; i < KT_FLOATS; i += 512) {
        gkh[i] = sKhi[i];
        gkl[i] = sKlo[i];
    }
    for (int i = threadIdx.x; i < VT_FLOATS; i += 512)
        gv[i] = sV[i];
}

// ---------------------------------------------------------------------------
// Fused attention, cp.async pipelined (unchanged from R7).
// ---------------------------------------------------------------------------
#define SM_KB  0
#define SM_KLO 19968
#define SM_VS  29952
#define SM_QLO 36608
#define SM_PS  48896
#define ATTN_SMEM_FLOATS 57600
#define ATTN_SMEM_BYTES  (ATTN_SMEM_FLOATS*4)

__global__ __launch_bounds__(256, 1) void attn_mma(float* __restrict__ out)
{
    extern __shared__ float sm[];
    float* KB   = sm + SM_KB;
    float* Klo  = sm + SM_KLO;
    float* Vs   = sm + SM_VS;
    float* QLO  = sm + SM_QLO + (threadIdx.x >> 5) * (12 * 128);
    float* Pshi = sm + SM_PS  + (threadIdx.x >> 5) * (16 * 68);
    float* Qst  = sm + SM_KB;

    const int tid  = threadIdx.x;
    const int lane = tid & 31;
    const int w    = tid >> 5;
    const int r    = lane >> 2;
    const int c    = lane & 3;
    const int q0   = blockIdx.x * 128;
    const int bh   = blockIdx.z * NHEAD + blockIdx.y;
    const size_t base = (size_t)blockIdx.z * (SEQ * CH) + (size_t)blockIdx.y * (HDIM * SEQ);

    const char* gkh = (const char*)(g_KhiP + (size_t)bh * NTILE * KT_FLOATS);
    const char* gkl = (const char*)(g_KloP + (size_t)bh * NTILE * KT_FLOATS);
    const char* gv  = (const char*)(g_VP   + (size_t)bh * NTILE * VT_FLOATS);
    const uint32_t sKB  = (uint32_t)__cvta_generic_to_shared(sm + SM_KB);
    const uint32_t sKLO = (uint32_t)__cvta_generic_to_shared(sm + SM_KLO);
    const uint32_t sVS  = (uint32_t)__cvta_generic_to_shared(sm + SM_VS);

    for (int idx = tid; idx < HDIM * 128; idx += 256) {
        int d = idx >> 7, q = idx & 127;
        Qst[d * 136 + q] = g_Q[base + (size_t)d * SEQ + q0 + q];
    }
    __syncthreads();

    uint32_t qhi[12][4];
    const int qm = w * 16 + r;
#pragma unroll
    for (int ks = 0; ks < 12; ks++) {
        float v0 = Qst[(8 * ks + c) * 136 + qm];
        float v1 = Qst[(8 * ks + c) * 136 + qm + 8];
        float v2 = Qst[(8 * ks + c + 4) * 136 + qm];
        float v3 = Qst[(8 * ks + c + 4) * 136 + qm + 8];
        qhi[ks][0] = f2tf(v0);
        qhi[ks][1] = f2tf(v1);
        qhi[ks][2] = f2tf(v2);
        qhi[ks][3] = f2tf(v3);
        float4 lo;
        lo.x = __uint_as_float(f2tf(v0 - __uint_as_float(qhi[ks][0])));
        lo.y = __uint_as_float(f2tf(v1 - __uint_as_float(qhi[ks][1])));
        lo.z = __uint_as_float(f2tf(v2 - __uint_as_float(qhi[ks][2])));
        lo.w = __uint_as_float(f2tf(v3 - __uint_as_float(qhi[ks][3])));
        *(float4*)&QLO[ks * 128 + lane * 4] = lo;
    }
    __syncthreads();

    {
        const int nch = KT_FLOATS / 4;
        for (int i = tid; i < nch; i += 256) {
            cp16(sKB  + i * 16, gkh + i * 16);
            cp16(sKLO + i * 16, gkl + i * 16);
        }
        CP_COMMIT();
    }

    float O[12][4];
#pragma unroll
    for (int f = 0; f < 12; f++)
#pragma unroll
        for (int j = 0; j < 4; j++) O[f][j] = 0.f;
    float mrow[2] = {-1e30f, -1e30f};
    float lrow[2] = {0.f, 0.f};

    for (int t = 0; t < NTILE; t++) {
        __syncthreads();

        {
            const char* src = gv + (size_t)t * VT_FLOATS * 4;
            const int nch = VT_FLOATS / 4;
            for (int i = tid; i < nch; i += 256)
                cp16(sVS + i * 16, src + i * 16);
            CP_COMMIT();
        }

        CP_WAIT(1);
        __syncthreads();

        const float* Khi = KB + (t & 1) * KT_FLOATS;

        float S[8][4];
#pragma unroll
        for (int f = 0; f < 8; f++)
#pragma unroll
            for (int j = 0; j < 4; j++) S[f][j] = 0.f;

#pragma unroll
        for (int ks = 0; ks < 12; ks++) {
            const int d0 = (8 * ks + c) * 104 + r * 12;
            const int d1 = (8 * ks + c + 4) * 104 + r * 12;
            float4 H0a = *(const float4*)&Khi[d0];
            float4 H0b = *(const float4*)&Khi[d0 + 4];
            float4 H1a = *(const float4*)&Khi[d1];
            float4 H1b = *(const float4*)&Khi[d1 + 4];
            float4 L0a = *(const float4*)&Klo[d0];
            float4 L0b = *(const float4*)&Klo[d0 + 4];
            float4 L1a = *(const float4*)&Klo[d1];
            float4 L1b = *(const float4*)&Klo[d1 + 4];
            float4 ql = *(const float4*)&QLO[ks * 128 + lane * 4];
            uint32_t qlo0 = __float_as_uint(ql.x), qlo1 = __float_as_uint(ql.y);
            uint32_t qlo2 = __float_as_uint(ql.z), qlo3 = __float_as_uint(ql.w);
            uint32_t bh0[8] = {__float_as_uint(H0a.x), __float_as_uint(H0a.y),
                               __float_as_uint(H0a.z), __float_as_uint(H0a.w),
                               __float_as_uint(H0b.x), __float_as_uint(H0b.y),
                               __float_as_uint(H0b.z), __float_as_uint(H0b.w)};
            uint32_t bh1[8] = {__float_as_uint(H1a.x), __float_as_uint(H1a.y),
                               __float_as_uint(H1a.z), __float_as_uint(H1a.w),
                               __float_as_uint(H1b.x), __float_as_uint(H1b.y),
                               __float_as_uint(H1b.z), __float_as_uint(H1b.w)};
            uint32_t bl0[8] = {__float_as_uint(L0a.x), __float_as_uint(L0a.y),
                               __float_as_uint(L0a.z), __float_as_uint(L0a.w),
                               __float_as_uint(L0b.x), __float_as_uint(L0b.y),
                               __float_as_uint(L0b.z), __float_as_uint(L0b.w)};
            uint32_t bl1[8] = {__float_as_uint(L1a.x), __float_as_uint(L1a.y),
                               __float_as_uint(L1a.z), __float_as_uint(L1a.w),
                               __float_as_uint(L1b.x), __float_as_uint(L1b.y),
                               __float_as_uint(L1b.z), __float_as_uint(L1b.w)};
#pragma unroll
            for (int f = 0; f < 8; f++)
                mma_tf32(S[f][0], S[f][1], S[f][2], S[f][3],
                         qhi[ks][0], qhi[ks][1], qhi[ks][2], qhi[ks][3],
                         bh0[f], bh1[f]);
#pragma unroll
            for (int f = 0; f < 8; f++)
                mma_tf32(S[f][0], S[f][1], S[f][2], S[f][3],
                         qhi[ks][0], qhi[ks][1], qhi[ks][2], qhi[ks][3],
                         bl0[f], bl1[f]);
#pragma unroll
            for (int f = 0; f < 8; f++)
                mma_tf32(S[f][0], S[f][1], S[f][2], S[f][3],
                         qlo0, qlo1, qlo2, qlo3,
                         bh0[f], bh1[f]);
        }

#pragma unroll
        for (int half = 0; half < 2; half++) {
            float mx = -1e30f;
#pragma unroll
            for (int f = 0; f < 8; f++)
                mx = fmaxf(mx, fmaxf(S[f][2 * half], S[f][2 * half + 1]));
            mx = fmaxf(mx, __shfl_xor_sync(0xFFFFFFFFu, mx, 1));
            mx = fmaxf(mx, __shfl_xor_sync(0xFFFFFFFFu, mx, 2));
            float mnew = fmaxf(mrow[half], mx);
            float al = __expf(mrow[half] - mnew);
            float rs = 0.f;
#pragma unroll
            for (int f = 0; f < 8; f++) {
                float p0 = __expf(S[f][2 * half] - mnew);
                float p1 = __expf(S[f][2 * half + 1] - mnew);
                rs += p0 + p1;
                *(float2*)&Pshi[(r + 8 * half) * 68 + f * 8 + 2 * c] =
                    make_float2(__uint_as_float(f2tf(p0)), __uint_as_float(f2tf(p1)));
            }
            rs += __shfl_xor_sync(0xFFFFFFFFu, rs, 1);
            rs += __shfl_xor_sync(0xFFFFFFFFu, rs, 2);
            lrow[half] = lrow[half] * al + rs;
            mrow[half] = mnew;
#pragma unroll
            for (int f = 0; f < 12; f++) {
                O[f][2 * half]     *= al;
                O[f][2 * half + 1] *= al;
            }
        }

        CP_WAIT(0);
        __syncthreads();

        if (t < NTILE - 1) {
            const char* srch = gkh + (size_t)(t + 1) * KT_FLOATS * 4;
            const char* srcl = gkl + (size_t)(t + 1) * KT_FLOATS * 4;
            const uint32_t dsth = sKB + ((t + 1) & 1) * KT_FLOATS * 4;
            const int nch = KT_FLOATS / 4;
            for (int i = tid; i < nch; i += 256) {
                cp16(dsth + i * 16, srch + i * 16);
                cp16(sKLO + i * 16, srcl + i * 16);
            }
            CP_COMMIT();
        }

#pragma unroll
        for (int ks = 0; ks < 8; ks++) {
            uint32_t a0 = __float_as_uint(Pshi[r * 68 + ks * 8 + c]);
            uint32_t a1 = __float_as_uint(Pshi[(r + 8) * 68 + ks * 8 + c]);
            uint32_t a2 = __float_as_uint(Pshi[r * 68 + ks * 8 + c + 4]);
            uint32_t a3 = __float_as_uint(Pshi[(r + 8) * 68 + ks * 8 + c + 4]);
            const int vb0 = (8 * ks + c) * 104 + r * 12;
            const int vb1 = (8 * ks + c + 4) * 104 + r * 12;
            float4 V0a = *(const float4*)&Vs[vb0];
            float4 V0b = *(const float4*)&Vs[vb0 + 4];
            float4 V0c = *(const float4*)&Vs[vb0 + 8];
            float4 V1a = *(const float4*)&Vs[vb1];
            float4 V1b = *(const float4*)&Vs[vb1 + 4];
            float4 V1c = *(const float4*)&Vs[vb1 + 8];
            uint32_t b0[12] = {__float_as_uint(V0a.x), __float_as_uint(V0a.y),
                               __float_as_uint(V0a.z), __float_as_uint(V0a.w),
                               __float_as_uint(V0b.x), __float_as_uint(V0b.y),
                               __float_as_uint(V0b.z), __float_as_uint(V0b.w),
                               __float_as_uint(V0c.x), __float_as_uint(V0c.y),
                               __float_as_uint(V0c.z), __float_as_uint(V0c.w)};
            uint32_t b1[12] = {__float_as_uint(V1a.x), __float_as_uint(V1a.y),
                               __float_as_uint(V1a.z), __float_as_uint(V1a.w),
                               __float_as_uint(V1b.x), __float_as_uint(V1b.y),
                               __float_as_uint(V1b.z), __float_as_uint(V1b.w),
                               __float_as_uint(V1c.x), __float_as_uint(V1c.y),
                               __float_as_uint(V1c.z), __float_as_uint(V1c.w)};
#pragma unroll
            for (int f = 0; f < 12; f++)
                mma_tf32(O[f][0], O[f][1], O[f][2], O[f][3],
                         a0, a1, a2, a3, b0[f], b1[f]);
        }
    }

    float inv0 = 1.f / lrow[0];
    float inv1 = 1.f / lrow[1];
#pragma unroll
    for (int f = 0; f < 12; f++) {
        int d0 = f * 8 + 2 * c;
        int qa = q0 + w * 16 + r;
        out[base + (size_t)d0 * SEQ + qa]           = O[f][0] * inv0;
        out[base + (size_t)(d0 + 1) * SEQ + qa]     = O[f][1] * inv0;
        out[base + (size_t)d0 * SEQ + qa + 8]       = O[f][2] * inv1;
        out[base + (size_t)(d0 + 1) * SEQ + qa + 8] = O[f][3] * inv1;
    }
}

// ---------------------------------------------------------------------------
extern "C" void kernel_launch(void* const* d_in, const int* in_sizes, int n_in,
                              void* d_out, int out_size)
{
    (void)in_sizes; (void)n_in; (void)out_size;
    const float* x1 = (const float*)d_in[0];
    const float* x2 = (const float*)d_in[1];
    const float* Wq = (const float*)d_in[2];
    const float* bq = (const float*)d_in[3];
    const float* Wk = (const float*)d_in[4];
    const float* bk = (const float*)d_in[5];
    const float* Wv = (const float*)d_in[6];
    const float* bv = (const float*)d_in[7];
    float* out = (float*)d_out;

    cudaFuncSetAttribute(proj_mma, cudaFuncAttributeMaxDynamicSharedMemorySize,
                         PROJ_SMEM_BYTES);
    cudaFuncSetAttribute(repack_kv, cudaFuncAttributeMaxDynamicSharedMemorySize,
                         RK_SMEM_BYTES);
    cudaFuncSetAttribute(attn_mma, cudaFuncAttributeMaxDynamicSharedMemorySize,
                         ATTN_SMEM_BYTES);

    proj_mma<<<dim3(9, 64, 3), 256, PROJ_SMEM_BYTES>>>(
        x1, x2, Wq, bq, Wk, bk, Wv, bv);
    repack_kv<<<dim3(NTILE, NHEAD, NB), 512, RK_SMEM_BYTES>>>();
    attn_mma<<<dim3(8, NHEAD, NB), 256, ATTN_SMEM_BYTES>>>(out);
}

// round 10
// speedup vs baseline: 1.1346x; 1.1346x over previous
#include <cuda_runtime.h>
#include <cstdint>

#define NB    8
#define SEQ   1024
#define CH    576
#define NHEAD 6
#define HDIM  96

// raw projection outputs (scrambled view [b][h][d][t])
__device__ float g_Q[NB*SEQ*CH];
__device__ float g_K[NB*SEQ*CH];
__device__ float g_V[NB*SEQ*CH];

// pre-packed W tiles: per (which, nt, kt): [32 k][72], slot = k*72 + wn*32 + (n&7)*4 + ((n>>3)&3)
#define WPT 2304            // 32*72
#define NKT 18
__device__ float g_WhiP[3*9*NKT*WPT];
__device__ float g_WloP[3*9*NKT*WPT];

// pre-decomposed, tile-layout K and V for the attention kernel (R7 layout).
#define KT_FLOATS 9984      // 96*104
#define VT_FLOATS 6656      // 64*104
#define NTILE     16
__device__ float g_KhiP[NB*NHEAD*NTILE*KT_FLOATS];
__device__ float g_KloP[NB*NHEAD*NTILE*KT_FLOATS];
__device__ float g_VP  [NB*NHEAD*NTILE*VT_FLOATS];

__device__ __forceinline__ uint32_t f2tf(float x) {
    uint32_t u;
    asm("cvt.rna.tf32.f32 %0, %1;" : "=r"(u) : "f"(x));
    return u;
}

__device__ __forceinline__ void mma_tf32(float& d0, float& d1, float& d2, float& d3,
                                         uint32_t a0, uint32_t a1, uint32_t a2, uint32_t a3,
                                         uint32_t b0, uint32_t b1) {
    asm volatile(
        "mma.sync.aligned.m16n8k8.row.col.f32.tf32.tf32.f32 "
        "{%0,%1,%2,%3},{%4,%5,%6,%7},{%8,%9},{%0,%1,%2,%3};"
        : "+f"(d0), "+f"(d1), "+f"(d2), "+f"(d3)
        : "r"(a0), "r"(a1), "r"(a2), "r"(a3), "r"(b0), "r"(b1));
}

__device__ __forceinline__ void cp16(uint32_t dst_smem, const void* src) {
    asm volatile("cp.async.cg.shared.global [%0], [%1], 16;\n"
                 :: "r"(dst_smem), "l"(src));
}
#define CP_COMMIT() asm volatile("cp.async.commit_group;\n" ::: "memory")
#define CP_WAIT(n)  asm volatile("cp.async.wait_group %0;\n" :: "n"(n) : "memory")

// ---------------------------------------------------------------------------
// prep_w: decompose W into tf32 hi/lo, packed tile layout. grid (9, 18, 3).
// slot within tile: k'*72 + (n'>>5)*32 + ((n'&31)&7)*4 + ((n'&31)>>3)
// ---------------------------------------------------------------------------
__global__ __launch_bounds__(256) void prep_w(
    const float* __restrict__ Wq, const float* __restrict__ Wk,
    const float* __restrict__ Wv)
{
    const int nt = blockIdx.x, kt = blockIdx.y, which = blockIdx.z;
    const float* W = (which == 0) ? Wq : (which == 1) ? Wk : Wv;
    const size_t tb = ((size_t)(which * 9 + nt) * NKT + kt) * WPT;
    for (int idx = threadIdx.x; idx < 64 * 32 / 4; idx += 256) {
        int n = idx >> 3;                 // 0..63
        int k4 = (idx & 7) * 4;           // 0,4,...,28
        float4 wv = *(const float4*)&W[(size_t)(nt * 64 + n) * CH + kt * 32 + k4];
        float ws[4] = {wv.x, wv.y, wv.z, wv.w};
        int half = n >> 5;
        int nn = n & 31;
        int slot = half * 32 + (nn & 7) * 4 + (nn >> 3);
#pragma unroll
        for (int j = 0; j < 4; j++) {
            uint32_t hb = f2tf(ws[j]);
            g_WhiP[tb + (k4 + j) * 72 + slot] = __uint_as_float(hb);
            g_WloP[tb + (k4 + j) * 72 + slot] =
                __uint_as_float(f2tf(ws[j] - __uint_as_float(hb)));
        }
    }
}

// ---------------------------------------------------------------------------
// Projection: Y = X @ W^T + bias.  SPLIT: 3x-tf32 (Q,K); !SPLIT: 1x tf32 (V).
// X converted in-kernel ([m][36] layout); W copied from pre-packed gmem.
// smem: Xhi[128*36] Xlo[128*36] Wph[2304] Wpl[2304]
// ---------------------------------------------------------------------------
#define PROJ_SMEM_SPLIT ((2*128*36 + 2*WPT) * 4)
#define PROJ_SMEM_ONE   ((128*36 + WPT) * 4)

template<bool SPLIT>
__global__ __launch_bounds__(256) void proj_mma(
    const float* __restrict__ x1, const float* __restrict__ x2,
    const float* __restrict__ bq, const float* __restrict__ bk,
    const float* __restrict__ bv)
{
    const int which = SPLIT ? blockIdx.z : 2;
    const float* X    = (which == 0) ? x1 : x2;
    const float* bias = (which == 0) ? bq : (which == 1) ? bk : bv;
    float*       Y    = (which == 0) ? g_Q : (which == 1) ? g_K : g_V;

    extern __shared__ float sp[];
    float* Xhi = sp;
    float* Xlo = SPLIT ? (sp + 128*36) : sp;
    float* Wph = sp + (SPLIT ? 2*128*36 : 128*36);
    float* Wpl = Wph + (SPLIT ? WPT : 0);

    const int tid  = threadIdx.x;
    const int lane = tid & 31;
    const int w    = tid >> 5;
    const int wm   = w & 3, wn = w >> 2;
    const int r    = lane >> 2, c = lane & 3;
    const int n0   = blockIdx.x * 64;
    const int m0   = blockIdx.y * 128;

    const float* WhiG = g_WhiP + ((size_t)(which * 9 + blockIdx.x) * NKT) * WPT;
    const float* WloG = g_WloP + ((size_t)(which * 9 + blockIdx.x) * NKT) * WPT;

    float acc[2][4][4];
#pragma unroll
    for (int mi = 0; mi < 2; mi++)
#pragma unroll
        for (int f = 0; f < 4; f++)
#pragma unroll
            for (int j = 0; j < 4; j++) acc[mi][f][j] = 0.f;

    const int lrow = tid >> 3;
    const int lcol = (tid & 7) * 4;

    for (int kt = 0; kt < NKT; kt++) {
        const int c0 = kt * 32;
        __syncthreads();
        // X tile convert (4 passes)
#pragma unroll
        for (int p = 0; p < 4; p++) {
            int m = lrow + p * 32;
            float4 xv = *(const float4*)&X[(size_t)(m0 + m) * CH + c0 + lcol];
            float xs[4] = {xv.x, xv.y, xv.z, xv.w};
#pragma unroll
            for (int j = 0; j < 4; j++) {
                uint32_t hb = f2tf(xs[j]);
                Xhi[m * 36 + lcol + j] = __uint_as_float(hb);
                if (SPLIT)
                    Xlo[m * 36 + lcol + j] =
                        __uint_as_float(f2tf(xs[j] - __uint_as_float(hb)));
            }
        }
        // W tile copy from pre-packed gmem (float4, coalesced, conflict-free)
        {
            const float* sh = WhiG + (size_t)kt * WPT;
            const float* sl = WloG + (size_t)kt * WPT;
#pragma unroll
            for (int p = 0; p < WPT / 4 / 256 + 1; p++) {
                int i = tid + p * 256;
                if (i < WPT / 4) {
                    *(float4*)&Wph[i * 4] = *(const float4*)&sh[i * 4];
                    if (SPLIT)
                        *(float4*)&Wpl[i * 4] = *(const float4*)&sl[i * 4];
                }
            }
        }
        __syncthreads();

#pragma unroll
        for (int ks = 0; ks < 4; ks++) {
            const int k = ks * 8 + c;
            uint32_t ahi[2][4], alo[2][4];
#pragma unroll
            for (int mi = 0; mi < 2; mi++) {
                int mm = wm * 32 + mi * 16;
                ahi[mi][0] = __float_as_uint(Xhi[(mm + r) * 36 + k]);
                ahi[mi][1] = __float_as_uint(Xhi[(mm + r + 8) * 36 + k]);
                ahi[mi][2] = __float_as_uint(Xhi[(mm + r) * 36 + k + 4]);
                ahi[mi][3] = __float_as_uint(Xhi[(mm + r + 8) * 36 + k + 4]);
                if (SPLIT) {
                    alo[mi][0] = __float_as_uint(Xlo[(mm + r) * 36 + k]);
                    alo[mi][1] = __float_as_uint(Xlo[(mm + r + 8) * 36 + k]);
                    alo[mi][2] = __float_as_uint(Xlo[(mm + r) * 36 + k + 4]);
                    alo[mi][3] = __float_as_uint(Xlo[(mm + r + 8) * 36 + k + 4]);
                }
            }
            // B fragments: one LDS.128 -> bhi[0..3][0], another -> bhi[0..3][1]
            const int kb0 = k * 72 + wn * 32 + r * 4;
            const int kb1 = (k + 4) * 72 + wn * 32 + r * 4;
            float4 BH0 = *(const float4*)&Wph[kb0];
            float4 BH1 = *(const float4*)&Wph[kb1];
            float bh0a[4] = {BH0.x, BH0.y, BH0.z, BH0.w};
            float bh1a[4] = {BH1.x, BH1.y, BH1.z, BH1.w};
            float bl0a[4], bl1a[4];
            if (SPLIT) {
                float4 BL0 = *(const float4*)&Wpl[kb0];
                float4 BL1 = *(const float4*)&Wpl[kb1];
                bl0a[0] = BL0.x; bl0a[1] = BL0.y; bl0a[2] = BL0.z; bl0a[3] = BL0.w;
                bl1a[0] = BL1.x; bl1a[1] = BL1.y; bl1a[2] = BL1.z; bl1a[3] = BL1.w;
            }
#pragma unroll
            for (int mi = 0; mi < 2; mi++)
#pragma unroll
                for (int f = 0; f < 4; f++) {
                    uint32_t b0 = __float_as_uint(bh0a[f]);
                    uint32_t b1 = __float_as_uint(bh1a[f]);
                    mma_tf32(acc[mi][f][0], acc[mi][f][1], acc[mi][f][2], acc[mi][f][3],
                             ahi[mi][0], ahi[mi][1], ahi[mi][2], ahi[mi][3],
                             b0, b1);
                    if (SPLIT) {
                        mma_tf32(acc[mi][f][0], acc[mi][f][1], acc[mi][f][2], acc[mi][f][3],
                                 ahi[mi][0], ahi[mi][1], ahi[mi][2], ahi[mi][3],
                                 __float_as_uint(bl0a[f]), __float_as_uint(bl1a[f]));
                        mma_tf32(acc[mi][f][0], acc[mi][f][1], acc[mi][f][2], acc[mi][f][3],
                                 alo[mi][0], alo[mi][1], alo[mi][2], alo[mi][3],
                                 b0, b1);
                    }
                }
        }
    }

#pragma unroll
    for (int mi = 0; mi < 2; mi++)
#pragma unroll
        for (int f = 0; f < 4; f++) {
            int n = n0 + wn * 32 + f * 8 + 2 * c;
            float b0 = bias[n], b1 = bias[n + 1];
            int m = m0 + wm * 32 + mi * 16 + r;
            float2 o0 = make_float2(acc[mi][f][0] + b0, acc[mi][f][1] + b1);
            float2 o1 = make_float2(acc[mi][f][2] + b0, acc[mi][f][3] + b1);
            *(float2*)&Y[(size_t)m * CH + n] = o0;
            *(float2*)&Y[(size_t)(m + 8) * CH + n] = o1;
        }
}

// ---------------------------------------------------------------------------
// Repack: K -> (hi,lo) tf32 tiles, V -> tf32 tiles, in attn smem layout.
// ---------------------------------------------------------------------------
#define RK_SMEM_BYTES ((2*KT_FLOATS + VT_FLOATS) * 4)

__global__ __launch_bounds__(512) void repack_kv()
{
    extern __shared__ float s[];
    float* sKhi = s;
    float* sKlo = s + KT_FLOATS;
    float* sV   = s + 2*KT_FLOATS;

    const int tile = blockIdx.x, h = blockIdx.y, b = blockIdx.z;
    const size_t base = (size_t)b*(SEQ*CH) + (size_t)h*(HDIM*SEQ) + (size_t)tile*64;

    for (int idx = threadIdx.x; idx < HDIM*64; idx += 512) {
        int d = idx >> 6, k = idx & 63;
        float kv = g_K[base + (size_t)d*SEQ + k];
        uint32_t hi = f2tf(kv);
        int slot = d*104 + (k&7)*12 + (k>>3);
        sKhi[slot] = __uint_as_float(hi);
        sKlo[slot] = __uint_as_float(f2tf(kv - __uint_as_float(hi)));
        float vv = g_V[base + (size_t)d*SEQ + k];
        sV[k*104 + (d&7)*12 + (d>>3)] = __uint_as_float(f2tf(vv));
    }
    __syncthreads();

    size_t tb = (size_t)((b*NHEAD + h)*NTILE + tile);
    float* gkh = g_KhiP + tb * KT_FLOATS;
    float* gkl = g_KloP + tb * KT_FLOATS;
    float* gv  = g_VP   + tb * VT_FLOATS;
    for (int i = threadIdx.x; i < KT_FLOATS; i += 512) {
        gkh[i] = sKhi[i];
        gkl[i] = sKlo[i];
    }
    for (int i = threadIdx.x; i < VT_FLOATS; i += 512)
        gv[i] = sV[i];
}

// ---------------------------------------------------------------------------
// Fused attention, cp.async pipelined (byte-identical to R7).
// ---------------------------------------------------------------------------
#define SM_KB  0
#define SM_KLO 19968
#define SM_VS  29952
#define SM_QLO 36608
#define SM_PS  48896
#define ATTN_SMEM_FLOATS 57600
#define ATTN_SMEM_BYTES  (ATTN_SMEM_FLOATS*4)

__global__ __launch_bounds__(256, 1) void attn_mma(float* __restrict__ out)
{
    extern __shared__ float sm[];
    float* KB   = sm + SM_KB;
    float* Klo  = sm + SM_KLO;
    float* Vs   = sm + SM_VS;
    float* QLO  = sm + SM_QLO + (threadIdx.x >> 5) * (12 * 128);
    float* Pshi = sm + SM_PS  + (threadIdx.x >> 5) * (16 * 68);
    float* Qst  = sm + SM_KB;

    const int tid  = threadIdx.x;
    const int lane = tid & 31;
    const int w    = tid >> 5;
    const int r    = lane >> 2;
    const int c    = lane & 3;
    const int q0   = blockIdx.x * 128;
    const int bh   = blockIdx.z * NHEAD + blockIdx.y;
    const size_t base = (size_t)blockIdx.z * (SEQ * CH) + (size_t)blockIdx.y * (HDIM * SEQ);

    const char* gkh = (const char*)(g_KhiP + (size_t)bh * NTILE * KT_FLOATS);
    const char* gkl = (const char*)(g_KloP + (size_t)bh * NTILE * KT_FLOATS);
    const char* gv  = (const char*)(g_VP   + (size_t)bh * NTILE * VT_FLOATS);
    const uint32_t sKB  = (uint32_t)__cvta_generic_to_shared(sm + SM_KB);
    const uint32_t sKLO = (uint32_t)__cvta_generic_to_shared(sm + SM_KLO);
    const uint32_t sVS  = (uint32_t)__cvta_generic_to_shared(sm + SM_VS);

    for (int idx = tid; idx < HDIM * 128; idx += 256) {
        int d = idx >> 7, q = idx & 127;
        Qst[d * 136 + q] = g_Q[base + (size_t)d * SEQ + q0 + q];
    }
    __syncthreads();

    uint32_t qhi[12][4];
    const int qm = w * 16 + r;
#pragma unroll
    for (int ks = 0; ks < 12; ks++) {
        float v0 = Qst[(8 * ks + c) * 136 + qm];
        float v1 = Qst[(8 * ks + c) * 136 + qm + 8];
        float v2 = Qst[(8 * ks + c + 4) * 136 + qm];
        float v3 = Qst[(8 * ks + c + 4) * 136 + qm + 8];
        qhi[ks][0] = f2tf(v0);
        qhi[ks][1] = f2tf(v1);
        qhi[ks][2] = f2tf(v2);
        qhi[ks][3] = f2tf(v3);
        float4 lo;
        lo.x = __uint_as_float(f2tf(v0 - __uint_as_float(qhi[ks][0])));
        lo.y = __uint_as_float(f2tf(v1 - __uint_as_float(qhi[ks][1])));
        lo.z = __uint_as_float(f2tf(v2 - __uint_as_float(qhi[ks][2])));
        lo.w = __uint_as_float(f2tf(v3 - __uint_as_float(qhi[ks][3])));
        *(float4*)&QLO[ks * 128 + lane * 4] = lo;
    }
    __syncthreads();

    {
        const int nch = KT_FLOATS / 4;
        for (int i = tid; i < nch; i += 256) {
            cp16(sKB  + i * 16, gkh + i * 16);
            cp16(sKLO + i * 16, gkl + i * 16);
        }
        CP_COMMIT();
    }

    float O[12][4];
#pragma unroll
    for (int f = 0; f < 12; f++)
#pragma unroll
        for (int j = 0; j < 4; j++) O[f][j] = 0.f;
    float mrow[2] = {-1e30f, -1e30f};
    float lrow[2] = {0.f, 0.f};

    for (int t = 0; t < NTILE; t++) {
        __syncthreads();

        {
            const char* src = gv + (size_t)t * VT_FLOATS * 4;
            const int nch = VT_FLOATS / 4;
            for (int i = tid; i < nch; i += 256)
                cp16(sVS + i * 16, src + i * 16);
            CP_COMMIT();
        }

        CP_WAIT(1);
        __syncthreads();

        const float* Khi = KB + (t & 1) * KT_FLOATS;

        float S[8][4];
#pragma unroll
        for (int f = 0; f < 8; f++)
#pragma unroll
            for (int j = 0; j < 4; j++) S[f][j] = 0.f;

#pragma unroll
        for (int ks = 0; ks < 12; ks++) {
            const int d0 = (8 * ks + c) * 104 + r * 12;
            const int d1 = (8 * ks + c + 4) * 104 + r * 12;
            float4 H0a = *(const float4*)&Khi[d0];
            float4 H0b = *(const float4*)&Khi[d0 + 4];
            float4 H1a = *(const float4*)&Khi[d1];
            float4 H1b = *(const float4*)&Khi[d1 + 4];
            float4 L0a = *(const float4*)&Klo[d0];
            float4 L0b = *(const float4*)&Klo[d0 + 4];
            float4 L1a = *(const float4*)&Klo[d1];
            float4 L1b = *(const float4*)&Klo[d1 + 4];
            float4 ql = *(const float4*)&QLO[ks * 128 + lane * 4];
            uint32_t qlo0 = __float_as_uint(ql.x), qlo1 = __float_as_uint(ql.y);
            uint32_t qlo2 = __float_as_uint(ql.z), qlo3 = __float_as_uint(ql.w);
            uint32_t bh0[8] = {__float_as_uint(H0a.x), __float_as_uint(H0a.y),
                               __float_as_uint(H0a.z), __float_as_uint(H0a.w),
                               __float_as_uint(H0b.x), __float_as_uint(H0b.y),
                               __float_as_uint(H0b.z), __float_as_uint(H0b.w)};
            uint32_t bh1[8] = {__float_as_uint(H1a.x), __float_as_uint(H1a.y),
                               __float_as_uint(H1a.z), __float_as_uint(H1a.w),
                               __float_as_uint(H1b.x), __float_as_uint(H1b.y),
                               __float_as_uint(H1b.z), __float_as_uint(H1b.w)};
            uint32_t bl0[8] = {__float_as_uint(L0a.x), __float_as_uint(L0a.y),
                               __float_as_uint(L0a.z), __float_as_uint(L0a.w),
                               __float_as_uint(L0b.x), __float_as_uint(L0b.y),
                               __float_as_uint(L0b.z), __float_as_uint(L0b.w)};
            uint32_t bl1[8] = {__float_as_uint(L1a.x), __float_as_uint(L1a.y),
                               __float_as_uint(L1a.z), __float_as_uint(L1a.w),
                               __float_as_uint(L1b.x), __float_as_uint(L1b.y),
                               __float_as_uint(L1b.z), __float_as_uint(L1b.w)};
#pragma unroll
            for (int f = 0; f < 8; f++)
                mma_tf32(S[f][0], S[f][1], S[f][2], S[f][3],
                         qhi[ks][0], qhi[ks][1], qhi[ks][2], qhi[ks][3],
                         bh0[f], bh1[f]);
#pragma unroll
            for (int f = 0; f < 8; f++)
                mma_tf32(S[f][0], S[f][1], S[f][2], S[f][3],
                         qhi[ks][0], qhi[ks][1], qhi[ks][2], qhi[ks][3],
                         bl0[f], bl1[f]);
#pragma unroll
            for (int f = 0; f < 8; f++)
                mma_tf32(S[f][0], S[f][1], S[f][2], S[f][3],
                         qlo0, qlo1, qlo2, qlo3,
                         bh0[f], bh1[f]);
        }

#pragma unroll
        for (int half = 0; half < 2; half++) {
            float mx = -1e30f;
#pragma unroll
            for (int f = 0; f < 8; f++)
                mx = fmaxf(mx, fmaxf(S[f][2 * half], S[f][2 * half + 1]));
            mx = fmaxf(mx, __shfl_xor_sync(0xFFFFFFFFu, mx, 1));
            mx = fmaxf(mx, __shfl_xor_sync(0xFFFFFFFFu, mx, 2));
            float mnew = fmaxf(mrow[half], mx);
            float al = __expf(mrow[half] - mnew);
            float rs = 0.f;
#pragma unroll
            for (int f = 0; f < 8; f++) {
                float p0 = __expf(S[f][2 * half] - mnew);
                float p1 = __expf(S[f][2 * half + 1] - mnew);
                rs += p0 + p1;
                *(float2*)&Pshi[(r + 8 * half) * 68 + f * 8 + 2 * c] =
                    make_float2(__uint_as_float(f2tf(p0)), __uint_as_float(f2tf(p1)));
            }
            rs += __shfl_xor_sync(0xFFFFFFFFu, rs, 1);
            rs += __shfl_xor_sync(0xFFFFFFFFu, rs, 2);
            lrow[half] = lrow[half] * al + rs;
            mrow[half] = mnew;
#pragma unroll
            for (int f = 0; f < 12; f++) {
                O[f][2 * half]     *= al;
                O[f][2 * half + 1] *= al;
            }
        }

        CP_WAIT(0);
        __syncthreads();

        if (t < NTILE - 1) {
            const char* srch = gkh + (size_t)(t + 1) * KT_FLOATS * 4;
            const char* srcl = gkl + (size_t)(t + 1) * KT_FLOATS * 4;
            const uint32_t dsth = sKB + ((t + 1) & 1) * KT_FLOATS * 4;
            const int nch = KT_FLOATS / 4;
            for (int i = tid; i < nch; i += 256) {
                cp16(dsth + i * 16, srch + i * 16);
                cp16(sKLO + i * 16, srcl + i * 16);
            }
            CP_COMMIT();
        }

#pragma unroll
        for (int ks = 0; ks < 8; ks++) {
            uint32_t a0 = __float_as_uint(Pshi[r * 68 + ks * 8 + c]);
            uint32_t a1 = __float_as_uint(Pshi[(r + 8) * 68 + ks * 8 + c]);
            uint32_t a2 = __float_as_uint(Pshi[r * 68 + ks * 8 + c + 4]);
            uint32_t a3 = __float_as_uint(Pshi[(r + 8) * 68 + ks * 8 + c + 4]);
            const int vb0 = (8 * ks + c) * 104 + r * 12;
            const int vb1 = (8 * ks + c + 4) * 104 + r * 12;
            float4 V0a = *(const float4*)&Vs[vb0];
            float4 V0b = *(const float4*)&Vs[vb0 + 4];
            float4 V0c = *(const float4*)&Vs[vb0 + 8];
            float4 V1a = *(const float4*)&Vs[vb1];
            float4 V1b = *(const float4*)&Vs[vb1 + 4];
            float4 V1c = *(const float4*)&Vs[vb1 + 8];
            uint32_t b0[12] = {__float_as_uint(V0a.x), __float_as_uint(V0a.y),
                               __float_as_uint(V0a.z), __float_as_uint(V0a.w),
                               __float_as_uint(V0b.x), __float_as_uint(V0b.y),
                               __float_as_uint(V0b.z), __float_as_uint(V0b.w),
                               __float_as_uint(V0c.x), __float_as_uint(V0c.y),
                               __float_as_uint(V0c.z), __float_as_uint(V0c.w)};
            uint32_t b1[12] = {__float_as_uint(V1a.x), __float_as_uint(V1a.y),
                               __float_as_uint(V1a.z), __float_as_uint(V1a.w),
                               __float_as_uint(V1b.x), __float_as_uint(V1b.y),
                               __float_as_uint(V1b.z), __float_as_uint(V1b.w),
                               __float_as_uint(V1c.x), __float_as_uint(V1c.y),
                               __float_as_uint(V1c.z), __float_as_uint(V1c.w)};
#pragma unroll
            for (int f = 0; f < 12; f++)
                mma_tf32(O[f][0], O[f][1], O[f][2], O[f][3],
                         a0, a1, a2, a3, b0[f], b1[f]);
        }
    }

    float inv0 = 1.f / lrow[0];
    float inv1 = 1.f / lrow[1];
#pragma unroll
    for (int f = 0; f < 12; f++) {
        int d0 = f * 8 + 2 * c;
        int qa = q0 + w * 16 + r;
        out[base + (size_t)d0 * SEQ + qa]           = O[f][0] * inv0;
        out[base + (size_t)(d0 + 1) * SEQ + qa]     = O[f][1] * inv0;
        out[base + (size_t)d0 * SEQ + qa + 8]       = O[f][2] * inv1;
        out[base + (size_t)(d0 + 1) * SEQ + qa + 8] = O[f][3] * inv1;
    }
}

// ---------------------------------------------------------------------------
extern "C" void kernel_launch(void* const* d_in, const int* in_sizes, int n_in,
                              void* d_out, int out_size)
{
    (void)in_sizes; (void)n_in; (void)out_size;
    const float* x1 = (const float*)d_in[0];
    const float* x2 = (const float*)d_in[1];
    const float* Wq = (const float*)d_in[2];
    const float* bq = (const float*)d_in[3];
    const float* Wk = (const float*)d_in[4];
    const float* bk = (const float*)d_in[5];
    const float* Wv = (const float*)d_in[6];
    const float* bv = (const float*)d_in[7];
    float* out = (float*)d_out;

    cudaFuncSetAttribute(proj_mma<true>, cudaFuncAttributeMaxDynamicSharedMemorySize,
                         PROJ_SMEM_SPLIT);
    cudaFuncSetAttribute(proj_mma<false>, cudaFuncAttributeMaxDynamicSharedMemorySize,
                         PROJ_SMEM_ONE);
    cudaFuncSetAttribute(repack_kv, cudaFuncAttributeMaxDynamicSharedMemorySize,
                         RK_SMEM_BYTES);
    cudaFuncSetAttribute(attn_mma, cudaFuncAttributeMaxDynamicSharedMemorySize,
                         ATTN_SMEM_BYTES);

    prep_w<<<dim3(9, NKT, 3), 256>>>(Wq, Wk, Wv);
    proj_mma<true><<<dim3(9, 64, 2), 256, PROJ_SMEM_SPLIT>>>(x1, x2, bq, bk, bv);
    proj_mma<false><<<dim3(9, 64, 1), 256, PROJ_SMEM_ONE>>>(x1, x2, bq, bk, bv);
    repack_kv<<<dim3(NTILE, NHEAD, NB), 512, RK_SMEM_BYTES>>>();
    attn_mma<<<dim3(8, NHEAD, NB), 256, ATTN_SMEM_BYTES>>>(out);
}

// round 11
// speedup vs baseline: 1.2381x; 1.0912x over previous
#include <cuda_runtime.h>
#include <cstdint>

#define NB    8
#define SEQ   1024
#define CH    576
#define NHEAD 6
#define HDIM  96

// raw projection outputs (scrambled view [b][h][d][t])
__device__ float g_Q[NB*SEQ*CH];
__device__ float g_K[NB*SEQ*CH];
__device__ float g_V[NB*SEQ*CH];

// pre-decomposed, tile-layout K and V for the attention kernel.
// K tile: [96 rows][104], slot(d, k) = d*104 + (k&7)*12 + (k>>3)   (k = t&63)
// V tile: [64 rows][104], slot(k, d) = k*104 + (d&7)*12 + (d>>3)
#define KT_FLOATS 9984      // 96*104
#define VT_FLOATS 6656      // 64*104
#define NTILE     16
__device__ float g_KhiP[NB*NHEAD*NTILE*KT_FLOATS];
__device__ float g_KloP[NB*NHEAD*NTILE*KT_FLOATS];
__device__ float g_VP  [NB*NHEAD*NTILE*VT_FLOATS];

__device__ __forceinline__ uint32_t f2tf(float x) {
    uint32_t u;
    asm("cvt.rna.tf32.f32 %0, %1;" : "=r"(u) : "f"(x));
    return u;
}

__device__ __forceinline__ void mma_tf32(float& d0, float& d1, float& d2, float& d3,
                                         uint32_t a0, uint32_t a1, uint32_t a2, uint32_t a3,
                                         uint32_t b0, uint32_t b1) {
    asm volatile(
        "mma.sync.aligned.m16n8k8.row.col.f32.tf32.tf32.f32 "
        "{%0,%1,%2,%3},{%4,%5,%6,%7},{%8,%9},{%0,%1,%2,%3};"
        : "+f"(d0), "+f"(d1), "+f"(d2), "+f"(d3)
        : "r"(a0), "r"(a1), "r"(a2), "r"(a3), "r"(b0), "r"(b1));
}

__device__ __forceinline__ void cp16(uint32_t dst_smem, const void* src) {
    asm volatile("cp.async.cg.shared.global [%0], [%1], 16;\n"
                 :: "r"(dst_smem), "l"(src));
}
#define CP_COMMIT() asm volatile("cp.async.commit_group;\n" ::: "memory")
#define CP_WAIT(n)  asm volatile("cp.async.wait_group %0;\n" :: "n"(n) : "memory")

// ---------------------------------------------------------------------------
// Projection: Y = X @ W^T + bias.  SPLIT: 3x-tf32 (Q,K); !SPLIT: 1x tf32 (V).
// (byte-identical to R7 — verified best projection)
// ---------------------------------------------------------------------------
#define PROJ_SMEM_SPLIT ((2*128*36 + 2*64*36) * 4)
#define PROJ_SMEM_ONE   ((128*36 + 64*36) * 4)

template<bool SPLIT>
__global__ __launch_bounds__(256) void proj_mma(
    const float* __restrict__ x1, const float* __restrict__ x2,
    const float* __restrict__ Wq, const float* __restrict__ bq,
    const float* __restrict__ Wk, const float* __restrict__ bk,
    const float* __restrict__ Wv, const float* __restrict__ bv)
{
    const int which = SPLIT ? blockIdx.z : 2;
    const float* X    = (which == 0) ? x1 : x2;
    const float* W    = (which == 0) ? Wq : (which == 1) ? Wk : Wv;
    const float* bias = (which == 0) ? bq : (which == 1) ? bk : bv;
    float*       Y    = (which == 0) ? g_Q : (which == 1) ? g_K : g_V;

    extern __shared__ float sp[];
    float* Xhi = sp;
    float* Whi = sp + 128*36;
    float* Xlo = sp + 128*36 + 64*36;
    float* Wlo = sp + 2*128*36 + 64*36;

    const int tid  = threadIdx.x;
    const int lane = tid & 31;
    const int w    = tid >> 5;
    const int wm   = w & 3, wn = w >> 2;
    const int r    = lane >> 2, c = lane & 3;
    const int n0   = blockIdx.x * 64;
    const int m0   = blockIdx.y * 128;

    float acc[2][4][4];
#pragma unroll
    for (int mi = 0; mi < 2; mi++)
#pragma unroll
        for (int f = 0; f < 4; f++)
#pragma unroll
            for (int j = 0; j < 4; j++) acc[mi][f][j] = 0.f;

    const int lrow = tid >> 3;
    const int lcol = (tid & 7) * 4;

    for (int c0 = 0; c0 < CH; c0 += 32) {
        __syncthreads();
#pragma unroll
        for (int p = 0; p < 4; p++) {
            int m = lrow + p * 32;
            float4 xv = *(const float4*)&X[(size_t)(m0 + m) * CH + c0 + lcol];
            float xs[4] = {xv.x, xv.y, xv.z, xv.w};
#pragma unroll
            for (int j = 0; j < 4; j++) {
                uint32_t hb = f2tf(xs[j]);
                Xhi[m * 36 + lcol + j] = __uint_as_float(hb);
                if (SPLIT)
                    Xlo[m * 36 + lcol + j] =
                        __uint_as_float(f2tf(xs[j] - __uint_as_float(hb)));
            }
        }
#pragma unroll
        for (int p = 0; p < 2; p++) {
            int n = lrow + p * 32;
            float4 wv = *(const float4*)&W[(size_t)(n0 + n) * CH + c0 + lcol];
            float ws[4] = {wv.x, wv.y, wv.z, wv.w};
#pragma unroll
            for (int j = 0; j < 4; j++) {
                uint32_t hb = f2tf(ws[j]);
                Whi[n * 36 + lcol + j] = __uint_as_float(hb);
                if (SPLIT)
                    Wlo[n * 36 + lcol + j] =
                        __uint_as_float(f2tf(ws[j] - __uint_as_float(hb)));
            }
        }
        __syncthreads();

#pragma unroll
        for (int ks = 0; ks < 4; ks++) {
            const int k = ks * 8 + c;
            uint32_t ahi[2][4], alo[2][4], bhi[4][2], blo[4][2];
#pragma unroll
            for (int mi = 0; mi < 2; mi++) {
                int mm = wm * 32 + mi * 16;
                ahi[mi][0] = __float_as_uint(Xhi[(mm + r) * 36 + k]);
                ahi[mi][1] = __float_as_uint(Xhi[(mm + r + 8) * 36 + k]);
                ahi[mi][2] = __float_as_uint(Xhi[(mm + r) * 36 + k + 4]);
                ahi[mi][3] = __float_as_uint(Xhi[(mm + r + 8) * 36 + k + 4]);
                if (SPLIT) {
                    alo[mi][0] = __float_as_uint(Xlo[(mm + r) * 36 + k]);
                    alo[mi][1] = __float_as_uint(Xlo[(mm + r + 8) * 36 + k]);
                    alo[mi][2] = __float_as_uint(Xlo[(mm + r) * 36 + k + 4]);
                    alo[mi][3] = __float_as_uint(Xlo[(mm + r + 8) * 36 + k + 4]);
                }
            }
#pragma unroll
            for (int f = 0; f < 4; f++) {
                int nn = wn * 32 + f * 8 + r;
                bhi[f][0] = __float_as_uint(Whi[nn * 36 + k]);
                bhi[f][1] = __float_as_uint(Whi[nn * 36 + k + 4]);
                if (SPLIT) {
                    blo[f][0] = __float_as_uint(Wlo[nn * 36 + k]);
                    blo[f][1] = __float_as_uint(Wlo[nn * 36 + k + 4]);
                }
            }
#pragma unroll
            for (int mi = 0; mi < 2; mi++)
#pragma unroll
                for (int f = 0; f < 4; f++) {
                    mma_tf32(acc[mi][f][0], acc[mi][f][1], acc[mi][f][2], acc[mi][f][3],
                             ahi[mi][0], ahi[mi][1], ahi[mi][2], ahi[mi][3],
                             bhi[f][0], bhi[f][1]);
                    if (SPLIT) {
                        mma_tf32(acc[mi][f][0], acc[mi][f][1], acc[mi][f][2], acc[mi][f][3],
                                 ahi[mi][0], ahi[mi][1], ahi[mi][2], ahi[mi][3],
                                 blo[f][0], blo[f][1]);
                        mma_tf32(acc[mi][f][0], acc[mi][f][1], acc[mi][f][2], acc[mi][f][3],
                                 alo[mi][0], alo[mi][1], alo[mi][2], alo[mi][3],
                                 bhi[f][0], bhi[f][1]);
                    }
                }
        }
    }

#pragma unroll
    for (int mi = 0; mi < 2; mi++)
#pragma unroll
        for (int f = 0; f < 4; f++) {
            int n = n0 + wn * 32 + f * 8 + 2 * c;
            float b0 = bias[n], b1 = bias[n + 1];
            int m = m0 + wm * 32 + mi * 16 + r;
            float2 o0 = make_float2(acc[mi][f][0] + b0, acc[mi][f][1] + b1);
            float2 o1 = make_float2(acc[mi][f][2] + b0, acc[mi][f][3] + b1);
            *(float2*)&Y[(size_t)m * CH + n] = o0;
            *(float2*)&Y[(size_t)(m + 8) * CH + n] = o1;
        }
}

// ---------------------------------------------------------------------------
// Repack: K -> (hi,lo) tf32 tiles, V -> tf32 tiles, in attn smem layout.
// 512 threads (R10-verified: 57.9 -> 35.2 us).
// ---------------------------------------------------------------------------
#define RK_SMEM_BYTES ((2*KT_FLOATS + VT_FLOATS) * 4)

__global__ __launch_bounds__(512) void repack_kv()
{
    extern __shared__ float s[];
    float* sKhi = s;
    float* sKlo = s + KT_FLOATS;
    float* sV   = s + 2*KT_FLOATS;

    const int tile = blockIdx.x, h = blockIdx.y, b = blockIdx.z;
    const size_t base = (size_t)b*(SEQ*CH) + (size_t)h*(HDIM*SEQ) + (size_t)tile*64;

    for (int idx = threadIdx.x; idx < HDIM*64; idx += 512) {
        int d = idx >> 6, k = idx & 63;
        float kv = g_K[base + (size_t)d*SEQ + k];
        uint32_t hi = f2tf(kv);
        int slot = d*104 + (k&7)*12 + (k>>3);
        sKhi[slot] = __uint_as_float(hi);
        sKlo[slot] = __uint_as_float(f2tf(kv - __uint_as_float(hi)));
        float vv = g_V[base + (size_t)d*SEQ + k];
        sV[k*104 + (d&7)*12 + (d>>3)] = __uint_as_float(f2tf(vv));
    }
    __syncthreads();

    size_t tb = (size_t)((b*NHEAD + h)*NTILE + tile);
    float* gkh = g_KhiP + tb * KT_FLOATS;
    float* gkl = g_KloP + tb * KT_FLOATS;
    float* gv  = g_VP   + tb * VT_FLOATS;
    for (int i = threadIdx.x; i < KT_FLOATS; i += 512) {
        gkh[i] = sKhi[i];
        gkl[i] = sKlo[i];
    }
    for (int i = threadIdx.x; i < VT_FLOATS; i += 512)
        gv[i] = sV[i];
}

// ---------------------------------------------------------------------------
// Fused attention, cp.async pipelined (byte-identical to R7 — verified best).
// ---------------------------------------------------------------------------
#define SM_KB  0
#define SM_KLO 19968
#define SM_VS  29952
#define SM_QLO 36608
#define SM_PS  48896
#define ATTN_SMEM_FLOATS 57600
#define ATTN_SMEM_BYTES  (ATTN_SMEM_FLOATS*4)

__global__ __launch_bounds__(256, 1) void attn_mma(float* __restrict__ out)
{
    extern __shared__ float sm[];
    float* KB   = sm + SM_KB;
    float* Klo  = sm + SM_KLO;
    float* Vs   = sm + SM_VS;
    float* QLO  = sm + SM_QLO + (threadIdx.x >> 5) * (12 * 128);
    float* Pshi = sm + SM_PS  + (threadIdx.x >> 5) * (16 * 68);
    float* Qst  = sm + SM_KB;

    const int tid  = threadIdx.x;
    const int lane = tid & 31;
    const int w    = tid >> 5;
    const int r    = lane >> 2;
    const int c    = lane & 3;
    const int q0   = blockIdx.x * 128;
    const int bh   = blockIdx.z * NHEAD + blockIdx.y;
    const size_t base = (size_t)blockIdx.z * (SEQ * CH) + (size_t)blockIdx.y * (HDIM * SEQ);

    const char* gkh = (const char*)(g_KhiP + (size_t)bh * NTILE * KT_FLOATS);
    const char* gkl = (const char*)(g_KloP + (size_t)bh * NTILE * KT_FLOATS);
    const char* gv  = (const char*)(g_VP   + (size_t)bh * NTILE * VT_FLOATS);
    const uint32_t sKB  = (uint32_t)__cvta_generic_to_shared(sm + SM_KB);
    const uint32_t sKLO = (uint32_t)__cvta_generic_to_shared(sm + SM_KLO);
    const uint32_t sVS  = (uint32_t)__cvta_generic_to_shared(sm + SM_VS);

    for (int idx = tid; idx < HDIM * 128; idx += 256) {
        int d = idx >> 7, q = idx & 127;
        Qst[d * 136 + q] = g_Q[base + (size_t)d * SEQ + q0 + q];
    }
    __syncthreads();

    uint32_t qhi[12][4];
    const int qm = w * 16 + r;
#pragma unroll
    for (int ks = 0; ks < 12; ks++) {
        float v0 = Qst[(8 * ks + c) * 136 + qm];
        float v1 = Qst[(8 * ks + c) * 136 + qm + 8];
        float v2 = Qst[(8 * ks + c + 4) * 136 + qm];
        float v3 = Qst[(8 * ks + c + 4) * 136 + qm + 8];
        qhi[ks][0] = f2tf(v0);
        qhi[ks][1] = f2tf(v1);
        qhi[ks][2] = f2tf(v2);
        qhi[ks][3] = f2tf(v3);
        float4 lo;
        lo.x = __uint_as_float(f2tf(v0 - __uint_as_float(qhi[ks][0])));
        lo.y = __uint_as_float(f2tf(v1 - __uint_as_float(qhi[ks][1])));
        lo.z = __uint_as_float(f2tf(v2 - __uint_as_float(qhi[ks][2])));
        lo.w = __uint_as_float(f2tf(v3 - __uint_as_float(qhi[ks][3])));
        *(float4*)&QLO[ks * 128 + lane * 4] = lo;
    }
    __syncthreads();

    {
        const int nch = KT_FLOATS / 4;
        for (int i = tid; i < nch; i += 256) {
            cp16(sKB  + i * 16, gkh + i * 16);
            cp16(sKLO + i * 16, gkl + i * 16);
        }
        CP_COMMIT();
    }

    float O[12][4];
#pragma unroll
    for (int f = 0; f < 12; f++)
#pragma unroll
        for (int j = 0; j < 4; j++) O[f][j] = 0.f;
    float mrow[2] = {-1e30f, -1e30f};
    float lrow[2] = {0.f, 0.f};

    for (int t = 0; t < NTILE; t++) {
        __syncthreads();

        {
            const char* src = gv + (size_t)t * VT_FLOATS * 4;
            const int nch = VT_FLOATS / 4;
            for (int i = tid; i < nch; i += 256)
                cp16(sVS + i * 16, src + i * 16);
            CP_COMMIT();
        }

        CP_WAIT(1);
        __syncthreads();

        const float* Khi = KB + (t & 1) * KT_FLOATS;

        float S[8][4];
#pragma unroll
        for (int f = 0; f < 8; f++)
#pragma unroll
            for (int j = 0; j < 4; j++) S[f][j] = 0.f;

#pragma unroll
        for (int ks = 0; ks < 12; ks++) {
            const int d0 = (8 * ks + c) * 104 + r * 12;
            const int d1 = (8 * ks + c + 4) * 104 + r * 12;
            float4 H0a = *(const float4*)&Khi[d0];
            float4 H0b = *(const float4*)&Khi[d0 + 4];
            float4 H1a = *(const float4*)&Khi[d1];
            float4 H1b = *(const float4*)&Khi[d1 + 4];
            float4 L0a = *(const float4*)&Klo[d0];
            float4 L0b = *(const float4*)&Klo[d0 + 4];
            float4 L1a = *(const float4*)&Klo[d1];
            float4 L1b = *(const float4*)&Klo[d1 + 4];
            float4 ql = *(const float4*)&QLO[ks * 128 + lane * 4];
            uint32_t qlo0 = __float_as_uint(ql.x), qlo1 = __float_as_uint(ql.y);
            uint32_t qlo2 = __float_as_uint(ql.z), qlo3 = __float_as_uint(ql.w);
            uint32_t bh0[8] = {__float_as_uint(H0a.x), __float_as_uint(H0a.y),
                               __float_as_uint(H0a.z), __float_as_uint(H0a.w),
                               __float_as_uint(H0b.x), __float_as_uint(H0b.y),
                               __float_as_uint(H0b.z), __float_as_uint(H0b.w)};
            uint32_t bh1[8] = {__float_as_uint(H1a.x), __float_as_uint(H1a.y),
                               __float_as_uint(H1a.z), __float_as_uint(H1a.w),
                               __float_as_uint(H1b.x), __float_as_uint(H1b.y),
                               __float_as_uint(H1b.z), __float_as_uint(H1b.w)};
            uint32_t bl0[8] = {__float_as_uint(L0a.x), __float_as_uint(L0a.y),
                               __float_as_uint(L0a.z), __float_as_uint(L0a.w),
                               __float_as_uint(L0b.x), __float_as_uint(L0b.y),
                               __float_as_uint(L0b.z), __float_as_uint(L0b.w)};
            uint32_t bl1[8] = {__float_as_uint(L1a.x), __float_as_uint(L1a.y),
                               __float_as_uint(L1a.z), __float_as_uint(L1a.w),
                               __float_as_uint(L1b.x), __float_as_uint(L1b.y),
                               __float_as_uint(L1b.z), __float_as_uint(L1b.w)};
#pragma unroll
            for (int f = 0; f < 8; f++)
                mma_tf32(S[f][0], S[f][1], S[f][2], S[f][3],
                         qhi[ks][0], qhi[ks][1], qhi[ks][2], qhi[ks][3],
                         bh0[f], bh1[f]);
#pragma unroll
            for (int f = 0; f < 8; f++)
                mma_tf32(S[f][0], S[f][1], S[f][2], S[f][3],
                         qhi[ks][0], qhi[ks][1], qhi[ks][2], qhi[ks][3],
                         bl0[f], bl1[f]);
#pragma unroll
            for (int f = 0; f < 8; f++)
                mma_tf32(S[f][0], S[f][1], S[f][2], S[f][3],
                         qlo0, qlo1, qlo2, qlo3,
                         bh0[f], bh1[f]);
        }

#pragma unroll
        for (int half = 0; half < 2; half++) {
            float mx = -1e30f;
#pragma unroll
            for (int f = 0; f < 8; f++)
                mx = fmaxf(mx, fmaxf(S[f][2 * half], S[f][2 * half + 1]));
            mx = fmaxf(mx, __shfl_xor_sync(0xFFFFFFFFu, mx, 1));
            mx = fmaxf(mx, __shfl_xor_sync(0xFFFFFFFFu, mx, 2));
            float mnew = fmaxf(mrow[half], mx);
            float al = __expf(mrow[half] - mnew);
            float rs = 0.f;
#pragma unroll
            for (int f = 0; f < 8; f++) {
                float p0 = __expf(S[f][2 * half] - mnew);
                float p1 = __expf(S[f][2 * half + 1] - mnew);
                rs += p0 + p1;
                *(float2*)&Pshi[(r + 8 * half) * 68 + f * 8 + 2 * c] =
                    make_float2(__uint_as_float(f2tf(p0)), __uint_as_float(f2tf(p1)));
            }
            rs += __shfl_xor_sync(0xFFFFFFFFu, rs, 1);
            rs += __shfl_xor_sync(0xFFFFFFFFu, rs, 2);
            lrow[half] = lrow[half] * al + rs;
            mrow[half] = mnew;
#pragma unroll
            for (int f = 0; f < 12; f++) {
                O[f][2 * half]     *= al;
                O[f][2 * half + 1] *= al;
            }
        }

        CP_WAIT(0);
        __syncthreads();

        if (t < NTILE - 1) {
            const char* srch = gkh + (size_t)(t + 1) * KT_FLOATS * 4;
            const char* srcl = gkl + (size_t)(t + 1) * KT_FLOATS * 4;
            const uint32_t dsth = sKB + ((t + 1) & 1) * KT_FLOATS * 4;
            const int nch = KT_FLOATS / 4;
            for (int i = tid; i < nch; i += 256) {
                cp16(dsth + i * 16, srch + i * 16);
                cp16(sKLO + i * 16, srcl + i * 16);
            }
            CP_COMMIT();
        }

#pragma unroll
        for (int ks = 0; ks < 8; ks++) {
            uint32_t a0 = __float_as_uint(Pshi[r * 68 + ks * 8 + c]);
            uint32_t a1 = __float_as_uint(Pshi[(r + 8) * 68 + ks * 8 + c]);
            uint32_t a2 = __float_as_uint(Pshi[r * 68 + ks * 8 + c + 4]);
            uint32_t a3 = __float_as_uint(Pshi[(r + 8) * 68 + ks * 8 + c + 4]);
            const int vb0 = (8 * ks + c) * 104 + r * 12;
            const int vb1 = (8 * ks + c + 4) * 104 + r * 12;
            float4 V0a = *(const float4*)&Vs[vb0];
            float4 V0b = *(const float4*)&Vs[vb0 + 4];
            float4 V0c = *(const float4*)&Vs[vb0 + 8];
            float4 V1a = *(const float4*)&Vs[vb1];
            float4 V1b = *(const float4*)&Vs[vb1 + 4];
            float4 V1c = *(const float4*)&Vs[vb1 + 8];
            uint32_t b0[12] = {__float_as_uint(V0a.x), __float_as_uint(V0a.y),
                               __float_as_uint(V0a.z), __float_as_uint(V0a.w),
                               __float_as_uint(V0b.x), __float_as_uint(V0b.y),
                               __float_as_uint(V0b.z), __float_as_uint(V0b.w),
                               __float_as_uint(V0c.x), __float_as_uint(V0c.y),
                               __float_as_uint(V0c.z), __float_as_uint(V0c.w)};
            uint32_t b1[12] = {__float_as_uint(V1a.x), __float_as_uint(V1a.y),
                               __float_as_uint(V1a.z), __float_as_uint(V1a.w),
                               __float_as_uint(V1b.x), __float_as_uint(V1b.y),
                               __float_as_uint(V1b.z), __float_as_uint(V1b.w),
                               __float_as_uint(V1c.x), __float_as_uint(V1c.y),
                               __float_as_uint(V1c.z), __float_as_uint(V1c.w)};
#pragma unroll
            for (int f = 0; f < 12; f++)
                mma_tf32(O[f][0], O[f][1], O[f][2], O[f][3],
                         a0, a1, a2, a3, b0[f], b1[f]);
        }
    }

    float inv0 = 1.f / lrow[0];
    float inv1 = 1.f / lrow[1];
#pragma unroll
    for (int f = 0; f < 12; f++) {
        int d0 = f * 8 + 2 * c;
        int qa = q0 + w * 16 + r;
        out[base + (size_t)d0 * SEQ + qa]           = O[f][0] * inv0;
        out[base + (size_t)(d0 + 1) * SEQ + qa]     = O[f][1] * inv0;
        out[base + (size_t)d0 * SEQ + qa + 8]       = O[f][2] * inv1;
        out[base + (size_t)(d0 + 1) * SEQ + qa + 8] = O[f][3] * inv1;
    }
}

// ---------------------------------------------------------------------------
extern "C" void kernel_launch(void* const* d_in, const int* in_sizes, int n_in,
                              void* d_out, int out_size)
{
    (void)in_sizes; (void)n_in; (void)out_size;
    const float* x1 = (const float*)d_in[0];
    const float* x2 = (const float*)d_in[1];
    const float* Wq = (const float*)d_in[2];
    const float* bq = (const float*)d_in[3];
    const float* Wk = (const float*)d_in[4];
    const float* bk = (const float*)d_in[5];
    const float* Wv = (const float*)d_in[6];
    const float* bv = (const float*)d_in[7];
    float* out = (float*)d_out;

    cudaFuncSetAttribute(proj_mma<true>, cudaFuncAttributeMaxDynamicSharedMemorySize,
                         PROJ_SMEM_SPLIT);
    cudaFuncSetAttribute(proj_mma<false>, cudaFuncAttributeMaxDynamicSharedMemorySize,
                         PROJ_SMEM_ONE);
    cudaFuncSetAttribute(repack_kv, cudaFuncAttributeMaxDynamicSharedMemorySize,
                         RK_SMEM_BYTES);
    cudaFuncSetAttribute(attn_mma, cudaFuncAttributeMaxDynamicSharedMemorySize,
                         ATTN_SMEM_BYTES);

    proj_mma<true><<<dim3(9, 64, 2), 256, PROJ_SMEM_SPLIT>>>(
        x1, x2, Wq, bq, Wk, bk, Wv, bv);
    proj_mma<false><<<dim3(9, 64, 1), 256, PROJ_SMEM_ONE>>>(
        x1, x2, Wq, bq, Wk, bk, Wv, bv);
    repack_kv<<<dim3(NTILE, NHEAD, NB), 512, RK_SMEM_BYTES>>>();
    attn_mma<<<dim3(8, NHEAD, NB), 256, ATTN_SMEM_BYTES>>>(out);
}

// round 12
// speedup vs baseline: 1.3544x; 1.0939x over previous
#include <cuda_runtime.h>
#include <cstdint>

#define NB    8
#define SEQ   1024
#define CH    576
#define NHEAD 6
#define HDIM  96

// raw projection outputs (scrambled view [b][h][d][t])
__device__ float g_Q[NB*SEQ*CH];
__device__ float g_K[NB*SEQ*CH];
__device__ float g_V[NB*SEQ*CH];

// pre-decomposed, tile-layout K and V for the attention kernel.
// K tile: [96 rows][104], slot(d, k) = d*104 + (k&7)*12 + (k>>3)   (k = t&63)
// V tile: [64 rows][104], slot(k, d) = k*104 + (d&7)*12 + (d>>3)
#define KT_FLOATS 9984      // 96*104
#define VT_FLOATS 6656      // 64*104
#define NTILE     16
__device__ float g_KhiP[NB*NHEAD*NTILE*KT_FLOATS];
__device__ float g_KloP[NB*NHEAD*NTILE*KT_FLOATS];
__device__ float g_VP  [NB*NHEAD*NTILE*VT_FLOATS];

__device__ __forceinline__ uint32_t f2tf(float x) {
    uint32_t u;
    asm("cvt.rna.tf32.f32 %0, %1;" : "=r"(u) : "f"(x));
    return u;
}

__device__ __forceinline__ void mma_tf32(float& d0, float& d1, float& d2, float& d3,
                                         uint32_t a0, uint32_t a1, uint32_t a2, uint32_t a3,
                                         uint32_t b0, uint32_t b1) {
    asm volatile(
        "mma.sync.aligned.m16n8k8.row.col.f32.tf32.tf32.f32 "
        "{%0,%1,%2,%3},{%4,%5,%6,%7},{%8,%9},{%0,%1,%2,%3};"
        : "+f"(d0), "+f"(d1), "+f"(d2), "+f"(d3)
        : "r"(a0), "r"(a1), "r"(a2), "r"(a3), "r"(b0), "r"(b1));
}

__device__ __forceinline__ void cp16(uint32_t dst_smem, const void* src) {
    asm volatile("cp.async.cg.shared.global [%0], [%1], 16;\n"
                 :: "r"(dst_smem), "l"(src));
}
#define CP_COMMIT() asm volatile("cp.async.commit_group;\n" ::: "memory")
#define CP_WAIT(n)  asm volatile("cp.async.wait_group %0;\n" :: "n"(n) : "memory")

// ---------------------------------------------------------------------------
// Projection: Y = X @ W^T + bias.  SPLIT: 3x-tf32 (Q,K); !SPLIT: 1x tf32 (V).
// (byte-identical to R7/R11 — verified best projection)
// ---------------------------------------------------------------------------
#define PROJ_SMEM_SPLIT ((2*128*36 + 2*64*36) * 4)
#define PROJ_SMEM_ONE   ((128*36 + 64*36) * 4)

template<bool SPLIT>
__global__ __launch_bounds__(256) void proj_mma(
    const float* __restrict__ x1, const float* __restrict__ x2,
    const float* __restrict__ Wq, const float* __restrict__ bq,
    const float* __restrict__ Wk, const float* __restrict__ bk,
    const float* __restrict__ Wv, const float* __restrict__ bv)
{
    const int which = SPLIT ? blockIdx.z : 2;
    const float* X    = (which == 0) ? x1 : x2;
    const float* W    = (which == 0) ? Wq : (which == 1) ? Wk : Wv;
    const float* bias = (which == 0) ? bq : (which == 1) ? bk : bv;
    float*       Y    = (which == 0) ? g_Q : (which == 1) ? g_K : g_V;

    extern __shared__ float sp[];
    float* Xhi = sp;
    float* Whi = sp + 128*36;
    float* Xlo = sp + 128*36 + 64*36;
    float* Wlo = sp + 2*128*36 + 64*36;

    const int tid  = threadIdx.x;
    const int lane = tid & 31;
    const int w    = tid >> 5;
    const int wm   = w & 3, wn = w >> 2;
    const int r    = lane >> 2, c = lane & 3;
    const int n0   = blockIdx.x * 64;
    const int m0   = blockIdx.y * 128;

    float acc[2][4][4];
#pragma unroll
    for (int mi = 0; mi < 2; mi++)
#pragma unroll
        for (int f = 0; f < 4; f++)
#pragma unroll
            for (int j = 0; j < 4; j++) acc[mi][f][j] = 0.f;

    const int lrow = tid >> 3;
    const int lcol = (tid & 7) * 4;

    for (int c0 = 0; c0 < CH; c0 += 32) {
        __syncthreads();
#pragma unroll
        for (int p = 0; p < 4; p++) {
            int m = lrow + p * 32;
            float4 xv = *(const float4*)&X[(size_t)(m0 + m) * CH + c0 + lcol];
            float xs[4] = {xv.x, xv.y, xv.z, xv.w};
#pragma unroll
            for (int j = 0; j < 4; j++) {
                uint32_t hb = f2tf(xs[j]);
                Xhi[m * 36 + lcol + j] = __uint_as_float(hb);
                if (SPLIT)
                    Xlo[m * 36 + lcol + j] =
                        __uint_as_float(f2tf(xs[j] - __uint_as_float(hb)));
            }
        }
#pragma unroll
        for (int p = 0; p < 2; p++) {
            int n = lrow + p * 32;
            float4 wv = *(const float4*)&W[(size_t)(n0 + n) * CH + c0 + lcol];
            float ws[4] = {wv.x, wv.y, wv.z, wv.w};
#pragma unroll
            for (int j = 0; j < 4; j++) {
                uint32_t hb = f2tf(ws[j]);
                Whi[n * 36 + lcol + j] = __uint_as_float(hb);
                if (SPLIT)
                    Wlo[n * 36 + lcol + j] =
                        __uint_as_float(f2tf(ws[j] - __uint_as_float(hb)));
            }
        }
        __syncthreads();

#pragma unroll
        for (int ks = 0; ks < 4; ks++) {
            const int k = ks * 8 + c;
            uint32_t ahi[2][4], alo[2][4], bhi[4][2], blo[4][2];
#pragma unroll
            for (int mi = 0; mi < 2; mi++) {
                int mm = wm * 32 + mi * 16;
                ahi[mi][0] = __float_as_uint(Xhi[(mm + r) * 36 + k]);
                ahi[mi][1] = __float_as_uint(Xhi[(mm + r + 8) * 36 + k]);
                ahi[mi][2] = __float_as_uint(Xhi[(mm + r) * 36 + k + 4]);
                ahi[mi][3] = __float_as_uint(Xhi[(mm + r + 8) * 36 + k + 4]);
                if (SPLIT) {
                    alo[mi][0] = __float_as_uint(Xlo[(mm + r) * 36 + k]);
                    alo[mi][1] = __float_as_uint(Xlo[(mm + r + 8) * 36 + k]);
                    alo[mi][2] = __float_as_uint(Xlo[(mm + r) * 36 + k + 4]);
                    alo[mi][3] = __float_as_uint(Xlo[(mm + r + 8) * 36 + k + 4]);
                }
            }
#pragma unroll
            for (int f = 0; f < 4; f++) {
                int nn = wn * 32 + f * 8 + r;
                bhi[f][0] = __float_as_uint(Whi[nn * 36 + k]);
                bhi[f][1] = __float_as_uint(Whi[nn * 36 + k + 4]);
                if (SPLIT) {
                    blo[f][0] = __float_as_uint(Wlo[nn * 36 + k]);
                    blo[f][1] = __float_as_uint(Wlo[nn * 36 + k + 4]);
                }
            }
#pragma unroll
            for (int mi = 0; mi < 2; mi++)
#pragma unroll
                for (int f = 0; f < 4; f++) {
                    mma_tf32(acc[mi][f][0], acc[mi][f][1], acc[mi][f][2], acc[mi][f][3],
                             ahi[mi][0], ahi[mi][1], ahi[mi][2], ahi[mi][3],
                             bhi[f][0], bhi[f][1]);
                    if (SPLIT) {
                        mma_tf32(acc[mi][f][0], acc[mi][f][1], acc[mi][f][2], acc[mi][f][3],
                                 ahi[mi][0], ahi[mi][1], ahi[mi][2], ahi[mi][3],
                                 blo[f][0], blo[f][1]);
                        mma_tf32(acc[mi][f][0], acc[mi][f][1], acc[mi][f][2], acc[mi][f][3],
                                 alo[mi][0], alo[mi][1], alo[mi][2], alo[mi][3],
                                 bhi[f][0], bhi[f][1]);
                    }
                }
        }
    }

#pragma unroll
    for (int mi = 0; mi < 2; mi++)
#pragma unroll
        for (int f = 0; f < 4; f++) {
            int n = n0 + wn * 32 + f * 8 + 2 * c;
            float b0 = bias[n], b1 = bias[n + 1];
            int m = m0 + wm * 32 + mi * 16 + r;
            float2 o0 = make_float2(acc[mi][f][0] + b0, acc[mi][f][1] + b1);
            float2 o1 = make_float2(acc[mi][f][2] + b0, acc[mi][f][3] + b1);
            *(float2*)&Y[(size_t)m * CH + n] = o0;
            *(float2*)&Y[(size_t)(m + 8) * CH + n] = o1;
        }
}

// ---------------------------------------------------------------------------
// Repack: K -> (hi,lo) tf32 tiles, V -> tf32 tiles, in attn smem layout.
// 512 threads (R10/R11-verified).
// ---------------------------------------------------------------------------
#define RK_SMEM_BYTES ((2*KT_FLOATS + VT_FLOATS) * 4)

__global__ __launch_bounds__(512) void repack_kv()
{
    extern __shared__ float s[];
    float* sKhi = s;
    float* sKlo = s + KT_FLOATS;
    float* sV   = s + 2*KT_FLOATS;

    const int tile = blockIdx.x, h = blockIdx.y, b = blockIdx.z;
    const size_t base = (size_t)b*(SEQ*CH) + (size_t)h*(HDIM*SEQ) + (size_t)tile*64;

    for (int idx = threadIdx.x; idx < HDIM*64; idx += 512) {
        int d = idx >> 6, k = idx & 63;
        float kv = g_K[base + (size_t)d*SEQ + k];
        uint32_t hi = f2tf(kv);
        int slot = d*104 + (k&7)*12 + (k>>3);
        sKhi[slot] = __uint_as_float(hi);
        sKlo[slot] = __uint_as_float(f2tf(kv - __uint_as_float(hi)));
        float vv = g_V[base + (size_t)d*SEQ + k];
        sV[k*104 + (d&7)*12 + (d>>3)] = __uint_as_float(f2tf(vv));
    }
    __syncthreads();

    size_t tb = (size_t)((b*NHEAD + h)*NTILE + tile);
    float* gkh = g_KhiP + tb * KT_FLOATS;
    float* gkl = g_KloP + tb * KT_FLOATS;
    float* gv  = g_VP   + tb * VT_FLOATS;
    for (int i = threadIdx.x; i < KT_FLOATS; i += 512) {
        gkh[i] = sKhi[i];
        gkl[i] = sKlo[i];
    }
    for (int i = threadIdx.x; i < VT_FLOATS; i += 512)
        gv[i] = sV[i];
}

// ---------------------------------------------------------------------------
// Fused attention, cp.async pipelined.  S = qhi*(Khi+Klo): 2-term split
// (qlo term dropped -> QLO smem region and its setup removed entirely).
// smem (floats): KB 2*9984 | Klo 9984 | Vs 6656 | Pshi 8*16*68
//   total 45312 floats = 181248 B
// ---------------------------------------------------------------------------
#define SM_KB  0
#define SM_KLO 19968
#define SM_VS  29952
#define SM_PS  36608
#define ATTN_SMEM_FLOATS 45312
#define ATTN_SMEM_BYTES  (ATTN_SMEM_FLOATS*4)

__global__ __launch_bounds__(256, 1) void attn_mma(float* __restrict__ out)
{
    extern __shared__ float sm[];
    float* KB   = sm + SM_KB;
    float* Klo  = sm + SM_KLO;
    float* Vs   = sm + SM_VS;
    float* Pshi = sm + SM_PS + (threadIdx.x >> 5) * (16 * 68);
    float* Qst  = sm + SM_KB;   // staging, overwritten by K tiles later

    const int tid  = threadIdx.x;
    const int lane = tid & 31;
    const int w    = tid >> 5;
    const int r    = lane >> 2;
    const int c    = lane & 3;
    const int q0   = blockIdx.x * 128;
    const int bh   = blockIdx.z * NHEAD + blockIdx.y;
    const size_t base = (size_t)blockIdx.z * (SEQ * CH) + (size_t)blockIdx.y * (HDIM * SEQ);

    const char* gkh = (const char*)(g_KhiP + (size_t)bh * NTILE * KT_FLOATS);
    const char* gkl = (const char*)(g_KloP + (size_t)bh * NTILE * KT_FLOATS);
    const char* gv  = (const char*)(g_VP   + (size_t)bh * NTILE * VT_FLOATS);
    const uint32_t sKB  = (uint32_t)__cvta_generic_to_shared(sm + SM_KB);
    const uint32_t sKLO = (uint32_t)__cvta_generic_to_shared(sm + SM_KLO);
    const uint32_t sVS  = (uint32_t)__cvta_generic_to_shared(sm + SM_VS);

    // ---- stage Q, build hi fragments only ----
    for (int idx = tid; idx < HDIM * 128; idx += 256) {
        int d = idx >> 7, q = idx & 127;
        Qst[d * 136 + q] = g_Q[base + (size_t)d * SEQ + q0 + q];
    }
    __syncthreads();

    uint32_t qhi[12][4];
    const int qm = w * 16 + r;
#pragma unroll
    for (int ks = 0; ks < 12; ks++) {
        qhi[ks][0] = f2tf(Qst[(8 * ks + c) * 136 + qm]);
        qhi[ks][1] = f2tf(Qst[(8 * ks + c) * 136 + qm + 8]);
        qhi[ks][2] = f2tf(Qst[(8 * ks + c + 4) * 136 + qm]);
        qhi[ks][3] = f2tf(Qst[(8 * ks + c + 4) * 136 + qm + 8]);
    }
    __syncthreads();   // Qst reads done; K tiles may overwrite

    // ---- preload K tile 0 (hi -> buf0, lo) ----
    {
        const int nch = KT_FLOATS / 4;
        for (int i = tid; i < nch; i += 256) {
            cp16(sKB  + i * 16, gkh + i * 16);
            cp16(sKLO + i * 16, gkl + i * 16);
        }
        CP_COMMIT();
    }

    float O[12][4];
#pragma unroll
    for (int f = 0; f < 12; f++)
#pragma unroll
        for (int j = 0; j < 4; j++) O[f][j] = 0.f;
    float mrow[2] = {-1e30f, -1e30f};
    float lrow[2] = {0.f, 0.f};

    for (int t = 0; t < NTILE; t++) {
        __syncthreads();

        // issue V[t]
        {
            const char* src = gv + (size_t)t * VT_FLOATS * 4;
            const int nch = VT_FLOATS / 4;
            for (int i = tid; i < nch; i += 256)
                cp16(sVS + i * 16, src + i * 16);
            CP_COMMIT();
        }

        CP_WAIT(1);        // K[t] complete
        __syncthreads();

        const float* Khi = KB + (t & 1) * KT_FLOATS;

        // ---- S = qhi * (Khi + Klo)  (2-term tf32 split) ----
        float S[8][4];
#pragma unroll
        for (int f = 0; f < 8; f++)
#pragma unroll
            for (int j = 0; j < 4; j++) S[f][j] = 0.f;

#pragma unroll
        for (int ks = 0; ks < 12; ks++) {
            const int d0 = (8 * ks + c) * 104 + r * 12;
            const int d1 = (8 * ks + c + 4) * 104 + r * 12;
            float4 H0a = *(const float4*)&Khi[d0];
            float4 H0b = *(const float4*)&Khi[d0 + 4];
            float4 H1a = *(const float4*)&Khi[d1];
            float4 H1b = *(const float4*)&Khi[d1 + 4];
            float4 L0a = *(const float4*)&Klo[d0];
            float4 L0b = *(const float4*)&Klo[d0 + 4];
            float4 L1a = *(const float4*)&Klo[d1];
            float4 L1b = *(const float4*)&Klo[d1 + 4];
            uint32_t bh0[8] = {__float_as_uint(H0a.x), __float_as_uint(H0a.y),
                               __float_as_uint(H0a.z), __float_as_uint(H0a.w),
                               __float_as_uint(H0b.x), __float_as_uint(H0b.y),
                               __float_as_uint(H0b.z), __float_as_uint(H0b.w)};
            uint32_t bh1[8] = {__float_as_uint(H1a.x), __float_as_uint(H1a.y),
                               __float_as_uint(H1a.z), __float_as_uint(H1a.w),
                               __float_as_uint(H1b.x), __float_as_uint(H1b.y),
                               __float_as_uint(H1b.z), __float_as_uint(H1b.w)};
            uint32_t bl0[8] = {__float_as_uint(L0a.x), __float_as_uint(L0a.y),
                               __float_as_uint(L0a.z), __float_as_uint(L0a.w),
                               __float_as_uint(L0b.x), __float_as_uint(L0b.y),
                               __float_as_uint(L0b.z), __float_as_uint(L0b.w)};
            uint32_t bl1[8] = {__float_as_uint(L1a.x), __float_as_uint(L1a.y),
                               __float_as_uint(L1a.z), __float_as_uint(L1a.w),
                               __float_as_uint(L1b.x), __float_as_uint(L1b.y),
                               __float_as_uint(L1b.z), __float_as_uint(L1b.w)};
#pragma unroll
            for (int f = 0; f < 8; f++)
                mma_tf32(S[f][0], S[f][1], S[f][2], S[f][3],
                         qhi[ks][0], qhi[ks][1], qhi[ks][2], qhi[ks][3],
                         bh0[f], bh1[f]);
#pragma unroll
            for (int f = 0; f < 8; f++)
                mma_tf32(S[f][0], S[f][1], S[f][2], S[f][3],
                         qhi[ks][0], qhi[ks][1], qhi[ks][2], qhi[ks][3],
                         bl0[f], bl1[f]);
        }

        // ---- online softmax ----
#pragma unroll
        for (int half = 0; half < 2; half++) {
            float mx = -1e30f;
#pragma unroll
            for (int f = 0; f < 8; f++)
                mx = fmaxf(mx, fmaxf(S[f][2 * half], S[f][2 * half + 1]));
            mx = fmaxf(mx, __shfl_xor_sync(0xFFFFFFFFu, mx, 1));
            mx = fmaxf(mx, __shfl_xor_sync(0xFFFFFFFFu, mx, 2));
            float mnew = fmaxf(mrow[half], mx);
            float al = __expf(mrow[half] - mnew);
            float rs = 0.f;
#pragma unroll
            for (int f = 0; f < 8; f++) {
                float p0 = __expf(S[f][2 * half] - mnew);
                float p1 = __expf(S[f][2 * half + 1] - mnew);
                rs += p0 + p1;
                *(float2*)&Pshi[(r + 8 * half) * 68 + f * 8 + 2 * c] =
                    make_float2(__uint_as_float(f2tf(p0)), __uint_as_float(f2tf(p1)));
            }
            rs += __shfl_xor_sync(0xFFFFFFFFu, rs, 1);
            rs += __shfl_xor_sync(0xFFFFFFFFu, rs, 2);
            lrow[half] = lrow[half] * al + rs;
            mrow[half] = mnew;
#pragma unroll
            for (int f = 0; f < 12; f++) {
                O[f][2 * half]     *= al;
                O[f][2 * half + 1] *= al;
            }
        }

        CP_WAIT(0);        // V[t] complete
        __syncthreads();

        // issue K[t+1]
        if (t < NTILE - 1) {
            const char* srch = gkh + (size_t)(t + 1) * KT_FLOATS * 4;
            const char* srcl = gkl + (size_t)(t + 1) * KT_FLOATS * 4;
            const uint32_t dsth = sKB + ((t + 1) & 1) * KT_FLOATS * 4;
            const int nch = KT_FLOATS / 4;
            for (int i = tid; i < nch; i += 256) {
                cp16(dsth + i * 16, srch + i * 16);
                cp16(sKLO + i * 16, srcl + i * 16);
            }
            CP_COMMIT();
        }

        // ---- O += P @ V^T (single tf32) ----
#pragma unroll
        for (int ks = 0; ks < 8; ks++) {
            uint32_t a0 = __float_as_uint(Pshi[r * 68 + ks * 8 + c]);
            uint32_t a1 = __float_as_uint(Pshi[(r + 8) * 68 + ks * 8 + c]);
            uint32_t a2 = __float_as_uint(Pshi[r * 68 + ks * 8 + c + 4]);
            uint32_t a3 = __float_as_uint(Pshi[(r + 8) * 68 + ks * 8 + c + 4]);
            const int vb0 = (8 * ks + c) * 104 + r * 12;
            const int vb1 = (8 * ks + c + 4) * 104 + r * 12;
            float4 V0a = *(const float4*)&Vs[vb0];
            float4 V0b = *(const float4*)&Vs[vb0 + 4];
            float4 V0c = *(const float4*)&Vs[vb0 + 8];
            float4 V1a = *(const float4*)&Vs[vb1];
            float4 V1b = *(const float4*)&Vs[vb1 + 4];
            float4 V1c = *(const float4*)&Vs[vb1 + 8];
            uint32_t b0[12] = {__float_as_uint(V0a.x), __float_as_uint(V0a.y),
                               __float_as_uint(V0a.z), __float_as_uint(V0a.w),
                               __float_as_uint(V0b.x), __float_as_uint(V0b.y),
                               __float_as_uint(V0b.z), __float_as_uint(V0b.w),
                               __float_as_uint(V0c.x), __float_as_uint(V0c.y),
                               __float_as_uint(V0c.z), __float_as_uint(V0c.w)};
            uint32_t b1[12] = {__float_as_uint(V1a.x), __float_as_uint(V1a.y),
                               __float_as_uint(V1a.z), __float_as_uint(V1a.w),
                               __float_as_uint(V1b.x), __float_as_uint(V1b.y),
                               __float_as_uint(V1b.z), __float_as_uint(V1b.w),
                               __float_as_uint(V1c.x), __float_as_uint(V1c.y),
                               __float_as_uint(V1c.z), __float_as_uint(V1c.w)};
#pragma unroll
            for (int f = 0; f < 12; f++)
                mma_tf32(O[f][0], O[f][1], O[f][2], O[f][3],
                         a0, a1, a2, a3, b0[f], b1[f]);
        }
    }

    float inv0 = 1.f / lrow[0];
    float inv1 = 1.f / lrow[1];
#pragma unroll
    for (int f = 0; f < 12; f++) {
        int d0 = f * 8 + 2 * c;
        int qa = q0 + w * 16 + r;
        out[base + (size_t)d0 * SEQ + qa]           = O[f][0] * inv0;
        out[base + (size_t)(d0 + 1) * SEQ + qa]     = O[f][1] * inv0;
        out[base + (size_t)d0 * SEQ + qa + 8]       = O[f][2] * inv1;
        out[base + (size_t)(d0 + 1) * SEQ + qa + 8] = O[f][3] * inv1;
    }
}

// ---------------------------------------------------------------------------
extern "C" void kernel_launch(void* const* d_in, const int* in_sizes, int n_in,
                              void* d_out, int out_size)
{
    (void)in_sizes; (void)n_in; (void)out_size;
    const float* x1 = (const float*)d_in[0];
    const float* x2 = (const float*)d_in[1];
    const float* Wq = (const float*)d_in[2];
    const float* bq = (const float*)d_in[3];
    const float* Wk = (const float*)d_in[4];
    const float* bk = (const float*)d_in[5];
    const float* Wv = (const float*)d_in[6];
    const float* bv = (const float*)d_in[7];
    float* out = (float*)d_out;

    cudaFuncSetAttribute(proj_mma<true>, cudaFuncAttributeMaxDynamicSharedMemorySize,
                         PROJ_SMEM_SPLIT);
    cudaFuncSetAttribute(proj_mma<false>, cudaFuncAttributeMaxDynamicSharedMemorySize,
                         PROJ_SMEM_ONE);
    cudaFuncSetAttribute(repack_kv, cudaFuncAttributeMaxDynamicSharedMemorySize,
                         RK_SMEM_BYTES);
    cudaFuncSetAttribute(attn_mma, cudaFuncAttributeMaxDynamicSharedMemorySize,
                         ATTN_SMEM_BYTES);

    proj_mma<true><<<dim3(9, 64, 2), 256, PROJ_SMEM_SPLIT>>>(
        x1, x2, Wq, bq, Wk, bk, Wv, bv);
    proj_mma<false><<<dim3(9, 64, 1), 256, PROJ_SMEM_ONE>>>(
        x1, x2, Wq, bq, Wk, bk, Wv, bv);
    repack_kv<<<dim3(NTILE, NHEAD, NB), 512, RK_SMEM_BYTES>>>();
    attn_mma<<<dim3(8, NHEAD, NB), 256, ATTN_SMEM_BYTES>>>(out);
}

// round 13
// speedup vs baseline: 1.5138x; 1.1178x over previous
#include <cuda_runtime.h>
#include <cstdint>

#define NB    8
#define SEQ   1024
#define CH    576
#define NHEAD 6
#define HDIM  96

// raw projection outputs (scrambled view [b][h][d][t])
__device__ float g_Q[NB*SEQ*CH];
__device__ float g_K[NB*SEQ*CH];
__device__ float g_V[NB*SEQ*CH];

// pre-decomposed, tile-layout K and V for the attention kernel.
// K tile: [96 rows][104], slot(d, k) = d*104 + (k&7)*12 + (k>>3)   (k = t&63)
// V tile: [64 rows][104], slot(k, d) = k*104 + (d&7)*12 + (d>>3)
#define KT_FLOATS 9984      // 96*104
#define VT_FLOATS 6656      // 64*104
#define NTILE     16
__device__ float g_KhiP[NB*NHEAD*NTILE*KT_FLOATS];
__device__ float g_KloP[NB*NHEAD*NTILE*KT_FLOATS];
__device__ float g_VP  [NB*NHEAD*NTILE*VT_FLOATS];

__device__ __forceinline__ uint32_t f2tf(float x) {
    uint32_t u;
    asm("cvt.rna.tf32.f32 %0, %1;" : "=r"(u) : "f"(x));
    return u;
}

__device__ __forceinline__ void mma_tf32(float& d0, float& d1, float& d2, float& d3,
                                         uint32_t a0, uint32_t a1, uint32_t a2, uint32_t a3,
                                         uint32_t b0, uint32_t b1) {
    asm volatile(
        "mma.sync.aligned.m16n8k8.row.col.f32.tf32.tf32.f32 "
        "{%0,%1,%2,%3},{%4,%5,%6,%7},{%8,%9},{%0,%1,%2,%3};"
        : "+f"(d0), "+f"(d1), "+f"(d2), "+f"(d3)
        : "r"(a0), "r"(a1), "r"(a2), "r"(a3), "r"(b0), "r"(b1));
}

__device__ __forceinline__ void cp16(uint32_t dst_smem, const void* src) {
    asm volatile("cp.async.cg.shared.global [%0], [%1], 16;\n"
                 :: "r"(dst_smem), "l"(src));
}
#define CP_COMMIT() asm volatile("cp.async.commit_group;\n" ::: "memory")
#define CP_WAIT(n)  asm volatile("cp.async.wait_group %0;\n" :: "n"(n) : "memory")

// ---------------------------------------------------------------------------
// Projection: Y = X @ W^T + bias.
// WSPLIT (Q,K): 2-term split  Y = Xhi*(Whi + Wlo)   (X-lo term dropped)
// !WSPLIT (V) : 1-term        Y = Xhi*Whi
// smem WSPLIT: Xhi[128*36] Whi[64*36] Wlo[64*36] = 9216 floats
// ---------------------------------------------------------------------------
#define PROJ_SMEM_SPLIT ((128*36 + 2*64*36) * 4)
#define PROJ_SMEM_ONE   ((128*36 + 64*36) * 4)

template<bool WSPLIT>
__global__ __launch_bounds__(256) void proj_mma(
    const float* __restrict__ x1, const float* __restrict__ x2,
    const float* __restrict__ Wq, const float* __restrict__ bq,
    const float* __restrict__ Wk, const float* __restrict__ bk,
    const float* __restrict__ Wv, const float* __restrict__ bv)
{
    const int which = WSPLIT ? blockIdx.z : 2;
    const float* X    = (which == 0) ? x1 : x2;
    const float* W    = (which == 0) ? Wq : (which == 1) ? Wk : Wv;
    const float* bias = (which == 0) ? bq : (which == 1) ? bk : bv;
    float*       Y    = (which == 0) ? g_Q : (which == 1) ? g_K : g_V;

    extern __shared__ float sp[];
    float* Xhi = sp;
    float* Whi = sp + 128*36;
    float* Wlo = sp + 128*36 + 64*36;   // WSPLIT only

    const int tid  = threadIdx.x;
    const int lane = tid & 31;
    const int w    = tid >> 5;
    const int wm   = w & 3, wn = w >> 2;
    const int r    = lane >> 2, c = lane & 3;
    const int n0   = blockIdx.x * 64;
    const int m0   = blockIdx.y * 128;

    float acc[2][4][4];
#pragma unroll
    for (int mi = 0; mi < 2; mi++)
#pragma unroll
        for (int f = 0; f < 4; f++)
#pragma unroll
            for (int j = 0; j < 4; j++) acc[mi][f][j] = 0.f;

    const int lrow = tid >> 3;
    const int lcol = (tid & 7) * 4;

    for (int c0 = 0; c0 < CH; c0 += 32) {
        __syncthreads();
#pragma unroll
        for (int p = 0; p < 4; p++) {
            int m = lrow + p * 32;
            float4 xv = *(const float4*)&X[(size_t)(m0 + m) * CH + c0 + lcol];
            float xs[4] = {xv.x, xv.y, xv.z, xv.w};
#pragma unroll
            for (int j = 0; j < 4; j++)
                Xhi[m * 36 + lcol + j] = __uint_as_float(f2tf(xs[j]));
        }
#pragma unroll
        for (int p = 0; p < 2; p++) {
            int n = lrow + p * 32;
            float4 wv = *(const float4*)&W[(size_t)(n0 + n) * CH + c0 + lcol];
            float ws[4] = {wv.x, wv.y, wv.z, wv.w};
#pragma unroll
            for (int j = 0; j < 4; j++) {
                uint32_t hb = f2tf(ws[j]);
                Whi[n * 36 + lcol + j] = __uint_as_float(hb);
                if (WSPLIT)
                    Wlo[n * 36 + lcol + j] =
                        __uint_as_float(f2tf(ws[j] - __uint_as_float(hb)));
            }
        }
        __syncthreads();

#pragma unroll
        for (int ks = 0; ks < 4; ks++) {
            const int k = ks * 8 + c;
            uint32_t ahi[2][4], bhi[4][2], blo[4][2];
#pragma unroll
            for (int mi = 0; mi < 2; mi++) {
                int mm = wm * 32 + mi * 16;
                ahi[mi][0] = __float_as_uint(Xhi[(mm + r) * 36 + k]);
                ahi[mi][1] = __float_as_uint(Xhi[(mm + r + 8) * 36 + k]);
                ahi[mi][2] = __float_as_uint(Xhi[(mm + r) * 36 + k + 4]);
                ahi[mi][3] = __float_as_uint(Xhi[(mm + r + 8) * 36 + k + 4]);
            }
#pragma unroll
            for (int f = 0; f < 4; f++) {
                int nn = wn * 32 + f * 8 + r;
                bhi[f][0] = __float_as_uint(Whi[nn * 36 + k]);
                bhi[f][1] = __float_as_uint(Whi[nn * 36 + k + 4]);
                if (WSPLIT) {
                    blo[f][0] = __float_as_uint(Wlo[nn * 36 + k]);
                    blo[f][1] = __float_as_uint(Wlo[nn * 36 + k + 4]);
                }
            }
#pragma unroll
            for (int mi = 0; mi < 2; mi++)
#pragma unroll
                for (int f = 0; f < 4; f++) {
                    mma_tf32(acc[mi][f][0], acc[mi][f][1], acc[mi][f][2], acc[mi][f][3],
                             ahi[mi][0], ahi[mi][1], ahi[mi][2], ahi[mi][3],
                             bhi[f][0], bhi[f][1]);
                    if (WSPLIT)
                        mma_tf32(acc[mi][f][0], acc[mi][f][1], acc[mi][f][2], acc[mi][f][3],
                                 ahi[mi][0], ahi[mi][1], ahi[mi][2], ahi[mi][3],
                                 blo[f][0], blo[f][1]);
                }
        }
    }

#pragma unroll
    for (int mi = 0; mi < 2; mi++)
#pragma unroll
        for (int f = 0; f < 4; f++) {
            int n = n0 + wn * 32 + f * 8 + 2 * c;
            float b0 = bias[n], b1 = bias[n + 1];
            int m = m0 + wm * 32 + mi * 16 + r;
            float2 o0 = make_float2(acc[mi][f][0] + b0, acc[mi][f][1] + b1);
            float2 o1 = make_float2(acc[mi][f][2] + b0, acc[mi][f][3] + b1);
            *(float2*)&Y[(size_t)m * CH + n] = o0;
            *(float2*)&Y[(size_t)(m + 8) * CH + n] = o1;
        }
}

// ---------------------------------------------------------------------------
// Repack: K -> (hi,lo) tf32 tiles, V -> tf32 tiles, in attn smem layout.
// (byte-identical to R12; 512 threads, verified)
// ---------------------------------------------------------------------------
#define RK_SMEM_BYTES ((2*KT_FLOATS + VT_FLOATS) * 4)

__global__ __launch_bounds__(512) void repack_kv()
{
    extern __shared__ float s[];
    float* sKhi = s;
    float* sKlo = s + KT_FLOATS;
    float* sV   = s + 2*KT_FLOATS;

    const int tile = blockIdx.x, h = blockIdx.y, b = blockIdx.z;
    const size_t base = (size_t)b*(SEQ*CH) + (size_t)h*(HDIM*SEQ) + (size_t)tile*64;

    for (int idx = threadIdx.x; idx < HDIM*64; idx += 512) {
        int d = idx >> 6, k = idx & 63;
        float kv = g_K[base + (size_t)d*SEQ + k];
        uint32_t hi = f2tf(kv);
        int slot = d*104 + (k&7)*12 + (k>>3);
        sKhi[slot] = __uint_as_float(hi);
        sKlo[slot] = __uint_as_float(f2tf(kv - __uint_as_float(hi)));
        float vv = g_V[base + (size_t)d*SEQ + k];
        sV[k*104 + (d&7)*12 + (d>>3)] = __uint_as_float(f2tf(vv));
    }
    __syncthreads();

    size_t tb = (size_t)((b*NHEAD + h)*NTILE + tile);
    float* gkh = g_KhiP + tb * KT_FLOATS;
    float* gkl = g_KloP + tb * KT_FLOATS;
    float* gv  = g_VP   + tb * VT_FLOATS;
    for (int i = threadIdx.x; i < KT_FLOATS; i += 512) {
        gkh[i] = sKhi[i];
        gkl[i] = sKlo[i];
    }
    for (int i = threadIdx.x; i < VT_FLOATS; i += 512)
        gv[i] = sV[i];
}

// ---------------------------------------------------------------------------
// Fused attention (byte-identical to R12): S = qhi*(Khi+Klo), PV single tf32.
// ---------------------------------------------------------------------------
#define SM_KB  0
#define SM_KLO 19968
#define SM_VS  29952
#define SM_PS  36608
#define ATTN_SMEM_FLOATS 45312
#define ATTN_SMEM_BYTES  (ATTN_SMEM_FLOATS*4)

__global__ __launch_bounds__(256, 1) void attn_mma(float* __restrict__ out)
{
    extern __shared__ float sm[];
    float* KB   = sm + SM_KB;
    float* Klo  = sm + SM_KLO;
    float* Vs   = sm + SM_VS;
    float* Pshi = sm + SM_PS + (threadIdx.x >> 5) * (16 * 68);
    float* Qst  = sm + SM_KB;

    const int tid  = threadIdx.x;
    const int lane = tid & 31;
    const int w    = tid >> 5;
    const int r    = lane >> 2;
    const int c    = lane & 3;
    const int q0   = blockIdx.x * 128;
    const int bh   = blockIdx.z * NHEAD + blockIdx.y;
    const size_t base = (size_t)blockIdx.z * (SEQ * CH) + (size_t)blockIdx.y * (HDIM * SEQ);

    const char* gkh = (const char*)(g_KhiP + (size_t)bh * NTILE * KT_FLOATS);
    const char* gkl = (const char*)(g_KloP + (size_t)bh * NTILE * KT_FLOATS);
    const char* gv  = (const char*)(g_VP   + (size_t)bh * NTILE * VT_FLOATS);
    const uint32_t sKB  = (uint32_t)__cvta_generic_to_shared(sm + SM_KB);
    const uint32_t sKLO = (uint32_t)__cvta_generic_to_shared(sm + SM_KLO);
    const uint32_t sVS  = (uint32_t)__cvta_generic_to_shared(sm + SM_VS);

    for (int idx = tid; idx < HDIM * 128; idx += 256) {
        int d = idx >> 7, q = idx & 127;
        Qst[d * 136 + q] = g_Q[base + (size_t)d * SEQ + q0 + q];
    }
    __syncthreads();

    uint32_t qhi[12][4];
    const int qm = w * 16 + r;
#pragma unroll
    for (int ks = 0; ks < 12; ks++) {
        qhi[ks][0] = f2tf(Qst[(8 * ks + c) * 136 + qm]);
        qhi[ks][1] = f2tf(Qst[(8 * ks + c) * 136 + qm + 8]);
        qhi[ks][2] = f2tf(Qst[(8 * ks + c + 4) * 136 + qm]);
        qhi[ks][3] = f2tf(Qst[(8 * ks + c + 4) * 136 + qm + 8]);
    }
    __syncthreads();

    {
        const int nch = KT_FLOATS / 4;
        for (int i = tid; i < nch; i += 256) {
            cp16(sKB  + i * 16, gkh + i * 16);
            cp16(sKLO + i * 16, gkl + i * 16);
        }
        CP_COMMIT();
    }

    float O[12][4];
#pragma unroll
    for (int f = 0; f < 12; f++)
#pragma unroll
        for (int j = 0; j < 4; j++) O[f][j] = 0.f;
    float mrow[2] = {-1e30f, -1e30f};
    float lrow[2] = {0.f, 0.f};

    for (int t = 0; t < NTILE; t++) {
        __syncthreads();

        {
            const char* src = gv + (size_t)t * VT_FLOATS * 4;
            const int nch = VT_FLOATS / 4;
            for (int i = tid; i < nch; i += 256)
                cp16(sVS + i * 16, src + i * 16);
            CP_COMMIT();
        }

        CP_WAIT(1);
        __syncthreads();

        const float* Khi = KB + (t & 1) * KT_FLOATS;

        float S[8][4];
#pragma unroll
        for (int f = 0; f < 8; f++)
#pragma unroll
            for (int j = 0; j < 4; j++) S[f][j] = 0.f;

#pragma unroll
        for (int ks = 0; ks < 12; ks++) {
            const int d0 = (8 * ks + c) * 104 + r * 12;
            const int d1 = (8 * ks + c + 4) * 104 + r * 12;
            float4 H0a = *(const float4*)&Khi[d0];
            float4 H0b = *(const float4*)&Khi[d0 + 4];
            float4 H1a = *(const float4*)&Khi[d1];
            float4 H1b = *(const float4*)&Khi[d1 + 4];
            float4 L0a = *(const float4*)&Klo[d0];
            float4 L0b = *(const float4*)&Klo[d0 + 4];
            float4 L1a = *(const float4*)&Klo[d1];
            float4 L1b = *(const float4*)&Klo[d1 + 4];
            uint32_t bh0[8] = {__float_as_uint(H0a.x), __float_as_uint(H0a.y),
                               __float_as_uint(H0a.z), __float_as_uint(H0a.w),
                               __float_as_uint(H0b.x), __float_as_uint(H0b.y),
                               __float_as_uint(H0b.z), __float_as_uint(H0b.w)};
            uint32_t bh1[8] = {__float_as_uint(H1a.x), __float_as_uint(H1a.y),
                               __float_as_uint(H1a.z), __float_as_uint(H1a.w),
                               __float_as_uint(H1b.x), __float_as_uint(H1b.y),
                               __float_as_uint(H1b.z), __float_as_uint(H1b.w)};
            uint32_t bl0[8] = {__float_as_uint(L0a.x), __float_as_uint(L0a.y),
                               __float_as_uint(L0a.z), __float_as_uint(L0a.w),
                               __float_as_uint(L0b.x), __float_as_uint(L0b.y),
                               __float_as_uint(L0b.z), __float_as_uint(L0b.w)};
            uint32_t bl1[8] = {__float_as_uint(L1a.x), __float_as_uint(L1a.y),
                               __float_as_uint(L1a.z), __float_as_uint(L1a.w),
                               __float_as_uint(L1b.x), __float_as_uint(L1b.y),
                               __float_as_uint(L1b.z), __float_as_uint(L1b.w)};
#pragma unroll
            for (int f = 0; f < 8; f++)
                mma_tf32(S[f][0], S[f][1], S[f][2], S[f][3],
                         qhi[ks][0], qhi[ks][1], qhi[ks][2], qhi[ks][3],
                         bh0[f], bh1[f]);
#pragma unroll
            for (int f = 0; f < 8; f++)
                mma_tf32(S[f][0], S[f][1], S[f][2], S[f][3],
                         qhi[ks][0], qhi[ks][1], qhi[ks][2], qhi[ks][3],
                         bl0[f], bl1[f]);
        }

#pragma unroll
        for (int half = 0; half < 2; half++) {
            float mx = -1e30f;
#pragma unroll
            for (int f = 0; f < 8; f++)
                mx = fmaxf(mx, fmaxf(S[f][2 * half], S[f][2 * half + 1]));
            mx = fmaxf(mx, __shfl_xor_sync(0xFFFFFFFFu, mx, 1));
            mx = fmaxf(mx, __shfl_xor_sync(0xFFFFFFFFu, mx, 2));
            float mnew = fmaxf(mrow[half], mx);
            float al = __expf(mrow[half] - mnew);
            float rs = 0.f;
#pragma unroll
            for (int f = 0; f < 8; f++) {
                float p0 = __expf(S[f][2 * half] - mnew);
                float p1 = __expf(S[f][2 * half + 1] - mnew);
                rs += p0 + p1;
                *(float2*)&Pshi[(r + 8 * half) * 68 + f * 8 + 2 * c] =
                    make_float2(__uint_as_float(f2tf(p0)), __uint_as_float(f2tf(p1)));
            }
            rs += __shfl_xor_sync(0xFFFFFFFFu, rs, 1);
            rs += __shfl_xor_sync(0xFFFFFFFFu, rs, 2);
            lrow[half] = lrow[half] * al + rs;
            mrow[half] = mnew;
#pragma unroll
            for (int f = 0; f < 12; f++) {
                O[f][2 * half]     *= al;
                O[f][2 * half + 1] *= al;
            }
        }

        CP_WAIT(0);
        __syncthreads();

        if (t < NTILE - 1) {
            const char* srch = gkh + (size_t)(t + 1) * KT_FLOATS * 4;
            const char* srcl = gkl + (size_t)(t + 1) * KT_FLOATS * 4;
            const uint32_t dsth = sKB + ((t + 1) & 1) * KT_FLOATS * 4;
            const int nch = KT_FLOATS / 4;
            for (int i = tid; i < nch; i += 256) {
                cp16(dsth + i * 16, srch + i * 16);
                cp16(sKLO + i * 16, srcl + i * 16);
            }
            CP_COMMIT();
        }

#pragma unroll
        for (int ks = 0; ks < 8; ks++) {
            uint32_t a0 = __float_as_uint(Pshi[r * 68 + ks * 8 + c]);
            uint32_t a1 = __float_as_uint(Pshi[(r + 8) * 68 + ks * 8 + c]);
            uint32_t a2 = __float_as_uint(Pshi[r * 68 + ks * 8 + c + 4]);
            uint32_t a3 = __float_as_uint(Pshi[(r + 8) * 68 + ks * 8 + c + 4]);
            const int vb0 = (8 * ks + c) * 104 + r * 12;
            const int vb1 = (8 * ks + c + 4) * 104 + r * 12;
            float4 V0a = *(const float4*)&Vs[vb0];
            float4 V0b = *(const float4*)&Vs[vb0 + 4];
            float4 V0c = *(const float4*)&Vs[vb0 + 8];
            float4 V1a = *(const float4*)&Vs[vb1];
            float4 V1b = *(const float4*)&Vs[vb1 + 4];
            float4 V1c = *(const float4*)&Vs[vb1 + 8];
            uint32_t b0[12] = {__float_as_uint(V0a.x), __float_as_uint(V0a.y),
                               __float_as_uint(V0a.z), __float_as_uint(V0a.w),
                               __float_as_uint(V0b.x), __float_as_uint(V0b.y),
                               __float_as_uint(V0b.z), __float_as_uint(V0b.w),
                               __float_as_uint(V0c.x), __float_as_uint(V0c.y),
                               __float_as_uint(V0c.z), __float_as_uint(V0c.w)};
            uint32_t b1[12] = {__float_as_uint(V1a.x), __float_as_uint(V1a.y),
                               __float_as_uint(V1a.z), __float_as_uint(V1a.w),
                               __float_as_uint(V1b.x), __float_as_uint(V1b.y),
                               __float_as_uint(V1b.z), __float_as_uint(V1b.w),
                               __float_as_uint(V1c.x), __float_as_uint(V1c.y),
                               __float_as_uint(V1c.z), __float_as_uint(V1c.w)};
#pragma unroll
            for (int f = 0; f < 12; f++)
                mma_tf32(O[f][0], O[f][1], O[f][2], O[f][3],
                         a0, a1, a2, a3, b0[f], b1[f]);
        }
    }

    float inv0 = 1.f / lrow[0];
    float inv1 = 1.f / lrow[1];
#pragma unroll
    for (int f = 0; f < 12; f++) {
        int d0 = f * 8 + 2 * c;
        int qa = q0 + w * 16 + r;
        out[base + (size_t)d0 * SEQ + qa]           = O[f][0] * inv0;
        out[base + (size_t)(d0 + 1) * SEQ + qa]     = O[f][1] * inv0;
        out[base + (size_t)d0 * SEQ + qa + 8]       = O[f][2] * inv1;
        out[base + (size_t)(d0 + 1) * SEQ + qa + 8] = O[f][3] * inv1;
    }
}

// ---------------------------------------------------------------------------
extern "C" void kernel_launch(void* const* d_in, const int* in_sizes, int n_in,
                              void* d_out, int out_size)
{
    (void)in_sizes; (void)n_in; (void)out_size;
    const float* x1 = (const float*)d_in[0];
    const float* x2 = (const float*)d_in[1];
    const float* Wq = (const float*)d_in[2];
    const float* bq = (const float*)d_in[3];
    const float* Wk = (const float*)d_in[4];
    const float* bk = (const float*)d_in[5];
    const float* Wv = (const float*)d_in[6];
    const float* bv = (const float*)d_in[7];
    float* out = (float*)d_out;

    cudaFuncSetAttribute(proj_mma<true>, cudaFuncAttributeMaxDynamicSharedMemorySize,
                         PROJ_SMEM_SPLIT);
    cudaFuncSetAttribute(proj_mma<false>, cudaFuncAttributeMaxDynamicSharedMemorySize,
                         PROJ_SMEM_ONE);
    cudaFuncSetAttribute(repack_kv, cudaFuncAttributeMaxDynamicSharedMemorySize,
                         RK_SMEM_BYTES);
    cudaFuncSetAttribute(attn_mma, cudaFuncAttributeMaxDynamicSharedMemorySize,
                         ATTN_SMEM_BYTES);

    proj_mma<true><<<dim3(9, 64, 2), 256, PROJ_SMEM_SPLIT>>>(
        x1, x2, Wq, bq, Wk, bk, Wv, bv);
    proj_mma<false><<<dim3(9, 64, 1), 256, PROJ_SMEM_ONE>>>(
        x1, x2, Wq, bq, Wk, bk, Wv, bv);
    repack_kv<<<dim3(NTILE, NHEAD, NB), 512, RK_SMEM_BYTES>>>();
    attn_mma<<<dim3(8, NHEAD, NB), 256, ATTN_SMEM_BYTES>>>(out);
}